// round 14
// baseline (speedup 1.0000x reference)
#include <cuda_runtime.h>
#include <cuda_fp16.h>
#include <cstdint>
#include <stdint.h>
#include <math.h>

// Problem constants
#define Bdim 2
#define Sdim 2048
#define Hdim 2048
#define NHdim 16
#define Ddim 128
#define FFdim 8192
#define Mrows (Bdim*Sdim)   // 4096

// -------- scratch (device globals; no allocation) --------
__device__ float g_hidden[(size_t)Mrows*Hdim];   // residual+attn_out
__device__ float g_cos[Sdim*64];
__device__ float g_sin[Sdim*64];
__device__ __half g_qh[(size_t)Mrows*Hdim];      // [B,NH,S,D]
__device__ __half g_kh[(size_t)Mrows*Hdim];
__device__ __half g_vt[(size_t)Mrows*Hdim];      // [B,NH,D,S]
__device__ __half g_xh[(size_t)Mrows*Hdim];
__device__ __half g_ctxh[(size_t)Mrows*Hdim];
__device__ __half g_interh[(size_t)Mrows*FFdim];
__device__ __half g_wqkvh[(size_t)3*Hdim*Hdim];
__device__ __half g_wdh[(size_t)Hdim*Hdim];
__device__ __half g_w1h[(size_t)FFdim*Hdim];
__device__ __half g_w2h[(size_t)Hdim*FFdim];

// ============================ helpers ============================
__device__ __forceinline__ uint32_t smem_u32(const void* p) {
    uint32_t a;
    asm("{ .reg .u64 t; cvta.to.shared.u64 t, %1; cvt.u32.u64 %0, t; }" : "=r"(a) : "l"(p));
    return a;
}
__device__ __forceinline__ void ldsm4(uint32_t* r, uint32_t addr) {
    asm volatile("ldmatrix.sync.aligned.m8n8.x4.shared.b16 {%0,%1,%2,%3}, [%4];"
        : "=r"(r[0]), "=r"(r[1]), "=r"(r[2]), "=r"(r[3]) : "r"(addr));
}
__device__ __forceinline__ void mma16816(float* c, const uint32_t* a, uint32_t b0, uint32_t b1) {
    asm("mma.sync.aligned.m16n8k16.row.col.f32.f16.f16.f32 "
        "{%0,%1,%2,%3}, {%4,%5,%6,%7}, {%8,%9}, {%0,%1,%2,%3};"
        : "+f"(c[0]), "+f"(c[1]), "+f"(c[2]), "+f"(c[3])
        : "r"(a[0]), "r"(a[1]), "r"(a[2]), "r"(a[3]), "r"(b0), "r"(b1));
}
__device__ __forceinline__ void cp16(uint32_t dst, const void* src) {
    asm volatile("cp.async.cg.shared.global [%0], [%1], 16;"
        :: "r"(dst), "l"(__cvta_generic_to_global(src)) : "memory");
}
#define CP_COMMIT() asm volatile("cp.async.commit_group;" ::: "memory")
#define CP_WAIT(n)  asm volatile("cp.async.wait_group %0;" :: "n"(n) : "memory")

__device__ __forceinline__ float ex2(float x) {
    float r;
    asm("ex2.approx.ftz.f32 %0, %1;" : "=f"(r) : "f"(x));
    return r;
}
__device__ __forceinline__ uint32_t f22u(float a, float b) {
    __half2 h = __floats2half2_rn(a, b);
    return *(uint32_t*)&h;
}

// swizzled smem offset: rows of 64B (32 halfs), 16B chunk XOR (row>>1)&3
__device__ __forceinline__ uint32_t swoff(int row, int chunk) {
    return (uint32_t)(row * 64 + ((chunk ^ ((row >> 1) & 3)) << 4));
}

// ============================ weight convert kernel (float4 vectorized) ============================
__global__ void cvt_kernel(const float* __restrict__ in, __half* __restrict__ hi, int n8) {
    int i = blockIdx.x * blockDim.x + threadIdx.x;
    if (i >= n8) return;
    float4 a = ((const float4*)in)[(size_t)i * 2];
    float4 b = ((const float4*)in)[(size_t)i * 2 + 1];
    __half2 h0 = __floats2half2_rn(a.x, a.y), h1 = __floats2half2_rn(a.z, a.w);
    __half2 h2 = __floats2half2_rn(b.x, b.y), h3 = __floats2half2_rn(b.z, b.w);
    ((uint4*)hi)[i] = make_uint4(*(uint32_t*)&h0, *(uint32_t*)&h1,
                                 *(uint32_t*)&h2, *(uint32_t*)&h3);
}

// ============================ HMMA GEMM (fp32 acc, 256x128 tile) ============================
// EPI: 1 = bias+GELU -> Ch half ; 2 = bias+residual -> C fp32 ;
//      4 = QKV fused: bias + rope-split q/k + transpose v (Qout/Kout/VTout)
#define GBM 256
#define GBN 128
#define NSTAGE 3
#define STAGE1 24576     // Ah 16K | Wh 8K
#define HM_SMEM (NSTAGE*STAGE1)

template<int EPI>
__global__ void __launch_bounds__(512, 1) hgemm(
    const __half* __restrict__ Ah_, const __half* __restrict__ Wh_,
    const float* __restrict__ bias, const float* __restrict__ res,
    float* __restrict__ C, __half* __restrict__ Ch,
    __half* __restrict__ Kout, __half* __restrict__ VTout,
    int M, int N, int K)
{
    extern __shared__ char sm[];
    uint32_t smb = smem_u32(sm);
    int tid = threadIdx.x;
    int lane = tid & 31, wid = tid >> 5;
    int wm = (wid & 3) * 64;
    int wn = (wid >> 2) * 32;
    int bm = blockIdx.y * GBM, bn = blockIdx.x * GBN;

    int aidx = tid * 2;
    int arow = aidx >> 2, ach = aidx & 3;
    int wrow = tid >> 2, wch = tid & 3;
    const __half* pAh = Ah_ + (size_t)(bm + arow) * K + ach * 8;
    const __half* pWh = Wh_ + (size_t)(bn + wrow) * K + wch * 8;
    uint32_t dA0 = swoff(arow, ach), dA1 = swoff(arow, ach + 1);
    uint32_t dW  = swoff(wrow, wch);

    float acc[4][4][4];
#pragma unroll
    for (int i = 0; i < 4; i++)
#pragma unroll
        for (int j = 0; j < 4; j++)
#pragma unroll
            for (int q = 0; q < 4; q++) acc[i][j][q] = 0.f;

    int mat = lane >> 3, mr = lane & 7;
    int fr_row = (mat & 1) * 8 + mr;
    int fr_ch  = mat >> 1;

    const int NC = K >> 5;

    auto load_stage = [&](int c) {
        uint32_t base = smb + (uint32_t)(c % NSTAGE) * STAGE1;
        size_t ko = (size_t)c * 32;
        cp16(base + 0     + dA0, pAh + ko);
        cp16(base + 0     + dA1, pAh + ko + 8);
        cp16(base + 16384 + dW,  pWh + ko);
    };

#pragma unroll
    for (int c = 0; c < NSTAGE - 1; c++) { load_stage(c); CP_COMMIT(); }

    for (int c = 0; c < NC; c++) {
        CP_WAIT(NSTAGE - 2);
        __syncthreads();
        if (c + NSTAGE - 1 < NC) { load_stage(c + NSTAGE - 1); }
        CP_COMMIT();

        uint32_t base = smb + (uint32_t)(c % NSTAGE) * STAGE1;
#pragma unroll
        for (int kk = 0; kk < 2; kk++) {
            uint32_t ah[4][4], bh[2][4];
#pragma unroll
            for (int i = 0; i < 4; i++) {
                uint32_t off = swoff(wm + i * 16 + fr_row, kk * 2 + fr_ch);
                ldsm4(ah[i], base + 0 + off);
            }
#pragma unroll
            for (int g = 0; g < 2; g++) {
                uint32_t off = swoff(wn + g * 16 + fr_row, kk * 2 + fr_ch);
                ldsm4(bh[g], base + 16384 + off);
            }
#pragma unroll
            for (int i = 0; i < 4; i++) {
#pragma unroll
                for (int jj = 0; jj < 4; jj++) {
                    int g = jj >> 1, h = jj & 1;
                    mma16816(acc[i][jj], ah[i], bh[g][h], bh[g][h+2]);
                }
            }
        }
    }

    int tr = lane >> 2;
    int tc = (lane & 3) * 2;

    if (EPI == 4) {
        // ---- stage tile (+bias) into smem as fp16 ----
        __half* stg = (__half*)sm;
        const int SP = 136;   // padded row stride in halfs
        __syncthreads();      // all cp.async groups drained; stages now reusable
#pragma unroll
        for (int i = 0; i < 4; i++) {
#pragma unroll
            for (int jj = 0; jj < 4; jj++) {
                int n0l = wn + jj * 8 + tc;
                float b0 = bias[bn + n0l], b1 = bias[bn + n0l + 1];
#pragma unroll
                for (int half = 0; half < 2; half++) {
                    int rowl = wm + i * 16 + tr + half * 8;
                    float v0 = acc[i][jj][half * 2 + 0] + b0;
                    float v1 = acc[i][jj][half * 2 + 1] + b1;
                    *(__half2*)&stg[rowl * SP + n0l] = __floats2half2_rn(v0, v1);
                }
            }
        }
        __syncthreads();

        int n_block = bn >> 7;
        int head = n_block / 3, which = n_block - head * 3;
        int b = bm >> 11, sbase = bm & (Sdim - 1);

        if (which < 2) {
            // q or k: apply rope, write [B,NH,S,D]
            __half* dst = (which == 0) ? Ch : Kout;
            int row = tid >> 1, c0 = (tid & 1) * 64;
            int s = sbase + row;
            size_t obase = (((size_t)(b * NHdim + head)) * Sdim + s) * Ddim;
            const float* csp = g_cos + s * 64;
            const float* snp = g_sin + s * 64;
#pragma unroll
            for (int d = 0; d < 64; d += 2) {
                int dd = c0 + d;
                float v0 = __half2float(stg[row * SP + dd]);
                float v1 = __half2float(stg[row * SP + dd + 1]);
                int pd = dd ^ 64;
                float sgn = (dd < 64) ? -1.f : 1.f;
                float p0 = sgn * __half2float(stg[row * SP + pd]);
                float p1 = sgn * __half2float(stg[row * SP + pd + 1]);
                int di = dd & 63;
                *(__half2*)(dst + obase + dd) = __floats2half2_rn(
                    v0 * csp[di] + p0 * snp[di],
                    v1 * csp[di + 1] + p1 * snp[di + 1]);
            }
        } else {
            // v: transpose to [B,NH,D,S]; warp -> 8 d rows, lanes -> s pairs
            int d0 = (tid >> 5) * 8;
            int sl = (lane) * 2;
            __half* dstb = VTout + ((size_t)(b * NHdim + head)) * Ddim * Sdim;
#pragma unroll
            for (int dd = 0; dd < 8; dd++) {
                int d = d0 + dd;
                __half* drow = dstb + (size_t)d * Sdim + sbase;
#pragma unroll
                for (int so = 0; so < 256; so += 64) {
                    int s_ = sl + so;
                    __half2 hv = __halves2half2(stg[s_ * SP + d], stg[(s_ + 1) * SP + d]);
                    *(__half2*)(drow + s_) = hv;
                }
            }
        }
        return;
    }

#pragma unroll
    for (int i = 0; i < 4; i++) {
#pragma unroll
        for (int jj = 0; jj < 4; jj++) {
            int n0 = bn + wn + jj * 8 + tc;
            float b0 = bias[n0], b1 = bias[n0 + 1];
#pragma unroll
            for (int half = 0; half < 2; half++) {
                int m = bm + wm + i * 16 + tr + half * 8;
                size_t idx = (size_t)m * N + n0;
                float v0 = acc[i][jj][half * 2 + 0] + b0;
                float v1 = acc[i][jj][half * 2 + 1] + b1;
                if (EPI == 1) {
                    v0 = 0.5f * v0 * (1.0f + erff(v0 * 0.70710678118654752f));
                    v1 = 0.5f * v1 * (1.0f + erff(v1 * 0.70710678118654752f));
                    *(__half2*)(Ch + idx) = __floats2half2_rn(v0, v1);
                } else {
                    if (EPI == 2) { v0 += res[idx]; v1 += res[idx + 1]; }
                    *(float2*)(C + idx) = make_float2(v0, v1);
                }
            }
        }
    }
}

// ============================ LayerNorm -> fp16 ============================
__global__ void ln_kernel(const float* __restrict__ in, const float* __restrict__ w,
                          const float* __restrict__ b, __half* __restrict__ oh) {
    __shared__ float2 red[256];
    int row = blockIdx.x;
    const float* x = in + (size_t)row * Hdim;
    float s = 0.f, ss = 0.f;
    for (int i = threadIdx.x * 2; i < Hdim; i += 512) {
        float2 v = *(const float2*)(x + i);
        s += v.x + v.y;
        ss = fmaf(v.x, v.x, fmaf(v.y, v.y, ss));
    }
    red[threadIdx.x] = make_float2(s, ss);
    __syncthreads();
    for (int o = 128; o > 0; o >>= 1) {
        if (threadIdx.x < o) {
            float2 a = red[threadIdx.x], c = red[threadIdx.x + o];
            red[threadIdx.x] = make_float2(a.x + c.x, a.y + c.y);
        }
        __syncthreads();
    }
    float mean = red[0].x * (1.0f / Hdim);
    float var  = red[0].y * (1.0f / Hdim) - mean * mean;
    float rstd = rsqrtf(var + 1e-5f);
    for (int i = threadIdx.x * 2; i < Hdim; i += 512) {
        float2 v = *(const float2*)(x + i);
        float2 wv = *(const float2*)(w + i);
        float2 bv = *(const float2*)(b + i);
        float o0 = (v.x - mean) * rstd * wv.x + bv.x;
        float o1 = (v.y - mean) * rstd * wv.y + bv.y;
        *(__half2*)(oh + (size_t)row * Hdim + i) = __floats2half2_rn(o0, o1);
    }
}

// ============================ RoPE table (double precision trig) ============================
__global__ void rope_table_kernel() {
    int idx = blockIdx.x * blockDim.x + threadIdx.x;
    if (idx >= Sdim * 64) return;
    int s = idx >> 6, i = idx & 63;
    double invf = exp(-(double)i * (9.210340371976184 / 64.0)); // ln(10000)/64
    double th = (double)s * invf;
    g_cos[idx] = (float)cos(th);
    g_sin[idx] = (float)sin(th);
}

// ============================ HMMA flash attention (causal, Bc=128) ============================
#define AT_STAGE 65536
#define AT_SMEM (32768 + 2*AT_STAGE)

__global__ void __launch_bounds__(256, 1) attn_kernel() {
    extern __shared__ char sm[];
    uint32_t smb = smem_u32(sm);
    uint32_t qbase = smb;
    int tid = threadIdx.x;
    int lane = tid & 31, wid = tid >> 5;
    int qt = gridDim.x - 1 - blockIdx.x;
    int bh = blockIdx.y;

    const __half* Qg  = g_qh + ((size_t)bh * Sdim + (size_t)qt * 128) * Ddim;
    const __half* Kg  = g_kh + (size_t)bh * Sdim * Ddim;
    const __half* VTg = g_vt + (size_t)bh * Ddim * Sdim;

    {
        int row = tid >> 1, kb0 = (tid & 1) * 2;
#pragma unroll
        for (int i = 0; i < 8; i++) {
            int kb = kb0 + (i >> 2), ch = i & 3;
            cp16(qbase + kb * 8192 + swoff(row, ch), Qg + (size_t)row * 128 + kb * 32 + ch * 8);
        }
    }
    auto load_stage = [&](int kt) {
        uint32_t st = smb + 32768 + (uint32_t)(kt & 1) * AT_STAGE;
        const __half* kp = Kg + (size_t)kt * 128 * 128;
#pragma unroll
        for (int i = 0; i < 8; i++) {
            int idx = tid + i * 256;
            int krow = idx >> 4, kb = (idx >> 2) & 3, ch = idx & 3;
            cp16(st + kb * 8192 + swoff(krow, ch), kp + (size_t)krow * 128 + kb * 32 + ch * 8);
        }
        const __half* vp = VTg + (size_t)kt * 128;
#pragma unroll
        for (int i = 0; i < 8; i++) {
            int idx = tid + i * 256;
            int vs = idx >> 9, drow = (idx >> 2) & 127, ch = idx & 3;
            cp16(st + 32768 + vs * 8192 + swoff(drow, ch),
                 vp + (size_t)drow * Sdim + vs * 32 + ch * 8);
        }
    };

    int nkt = qt + 1;
    load_stage(0); CP_COMMIT();
    load_stage(1); CP_COMMIT();
    CP_WAIT(1);
    __syncthreads();

    int mat = lane >> 3, mr = lane & 7;
    int fr_row = (mat & 1) * 8 + mr, fr_ch = mat >> 1;
    int wm = wid * 16;
    int tr = lane >> 2, tq = lane & 3;

    uint32_t qf[8][4];
#pragma unroll
    for (int kk = 0; kk < 8; kk++)
        ldsm4(qf[kk], qbase + (kk >> 1) * 8192 + swoff(wm + fr_row, (kk & 1) * 2 + fr_ch));

    float o_acc[16][4];
#pragma unroll
    for (int j = 0; j < 16; j++)
#pragma unroll
        for (int q = 0; q < 4; q++) o_acc[j][q] = 0.f;
    float m_run[2] = { -INFINITY, -INFINITY };
    float l_run[2] = { 0.f, 0.f };

    const float SC = 0.08838834764831845f * 1.4426950408889634f;
    int rowg0 = qt * 128 + wm + tr;

    for (int kt = 0; kt < nkt; kt++) {
        if (kt > 0) { CP_WAIT(1); __syncthreads(); }
        uint32_t st = smb + 32768 + (uint32_t)(kt & 1) * AT_STAGE;

        float s_acc[16][4];
#pragma unroll
        for (int j = 0; j < 16; j++)
#pragma unroll
            for (int q = 0; q < 4; q++) s_acc[j][q] = 0.f;
#pragma unroll
        for (int kk = 0; kk < 8; kk++) {
#pragma unroll
            for (int g = 0; g < 8; g++) {
                uint32_t kf[4];
                ldsm4(kf, st + (kk >> 1) * 8192 + swoff(16 * g + fr_row, (kk & 1) * 2 + fr_ch));
                mma16816(s_acc[2 * g + 0], qf[kk], kf[0], kf[2]);
                mma16816(s_acc[2 * g + 1], qf[kk], kf[1], kf[3]);
            }
        }

#pragma unroll
        for (int j = 0; j < 16; j++)
#pragma unroll
            for (int q = 0; q < 4; q++) {
                int colg = kt * 128 + j * 8 + tq * 2 + (q & 1);
                int rowg = rowg0 + (q >> 1) * 8;
                float x = s_acc[j][q] * SC;
                s_acc[j][q] = (colg <= rowg) ? x : -1e30f;
            }
        float mrow0 = -1e30f, mrow1 = -1e30f;
#pragma unroll
        for (int j = 0; j < 16; j++) {
            mrow0 = fmaxf(mrow0, fmaxf(s_acc[j][0], s_acc[j][1]));
            mrow1 = fmaxf(mrow1, fmaxf(s_acc[j][2], s_acc[j][3]));
        }
        mrow0 = fmaxf(mrow0, __shfl_xor_sync(0xFFFFFFFF, mrow0, 1));
        mrow0 = fmaxf(mrow0, __shfl_xor_sync(0xFFFFFFFF, mrow0, 2));
        mrow1 = fmaxf(mrow1, __shfl_xor_sync(0xFFFFFFFF, mrow1, 1));
        mrow1 = fmaxf(mrow1, __shfl_xor_sync(0xFFFFFFFF, mrow1, 2));
        float mnew0 = fmaxf(m_run[0], mrow0);
        float mnew1 = fmaxf(m_run[1], mrow1);
        float alpha0 = ex2(m_run[0] - mnew0);
        float alpha1 = ex2(m_run[1] - mnew1);
        float rs0 = 0.f, rs1 = 0.f;
#pragma unroll
        for (int j = 0; j < 16; j++) {
            s_acc[j][0] = ex2(s_acc[j][0] - mnew0);
            s_acc[j][1] = ex2(s_acc[j][1] - mnew0);
            s_acc[j][2] = ex2(s_acc[j][2] - mnew1);
            s_acc[j][3] = ex2(s_acc[j][3] - mnew1);
            rs0 += s_acc[j][0] + s_acc[j][1];
            rs1 += s_acc[j][2] + s_acc[j][3];
        }
        rs0 += __shfl_xor_sync(0xFFFFFFFF, rs0, 1);
        rs0 += __shfl_xor_sync(0xFFFFFFFF, rs0, 2);
        rs1 += __shfl_xor_sync(0xFFFFFFFF, rs1, 1);
        rs1 += __shfl_xor_sync(0xFFFFFFFF, rs1, 2);
        l_run[0] = l_run[0] * alpha0 + rs0;
        l_run[1] = l_run[1] * alpha1 + rs1;
        m_run[0] = mnew0;
        m_run[1] = mnew1;
#pragma unroll
        for (int jj = 0; jj < 16; jj++) {
            o_acc[jj][0] *= alpha0; o_acc[jj][1] *= alpha0;
            o_acc[jj][2] *= alpha1; o_acc[jj][3] *= alpha1;
        }

        uint32_t pa[4][2][4];
#pragma unroll
        for (int vs = 0; vs < 4; vs++)
#pragma unroll
            for (int t = 0; t < 2; t++) {
                int j0 = vs * 4 + 2 * t;
                pa[vs][t][0] = f22u(s_acc[j0][0],   s_acc[j0][1]);
                pa[vs][t][1] = f22u(s_acc[j0][2],   s_acc[j0][3]);
                pa[vs][t][2] = f22u(s_acc[j0+1][0], s_acc[j0+1][1]);
                pa[vs][t][3] = f22u(s_acc[j0+1][2], s_acc[j0+1][3]);
            }

#pragma unroll
        for (int vs = 0; vs < 4; vs++) {
#pragma unroll
            for (int g = 0; g < 8; g++) {
#pragma unroll
                for (int t = 0; t < 2; t++) {
                    uint32_t vb[4];
                    ldsm4(vb, st + 32768 + vs * 8192 + swoff(16 * g + fr_row, t * 2 + fr_ch));
                    mma16816(o_acc[2 * g + 0], pa[vs][t], vb[0], vb[2]);
                    mma16816(o_acc[2 * g + 1], pa[vs][t], vb[1], vb[3]);
                }
            }
        }

        if (kt + 2 < nkt) {
            __syncthreads();
            load_stage(kt + 2);
            CP_COMMIT();
        } else {
            CP_COMMIT();
        }
    }

    float inv0 = 1.0f / l_run[0];
    float inv1 = 1.0f / l_run[1];
    int b = bh >> 4, h = bh & 15;
    int sg0 = qt * 128 + wm + tr;
#pragma unroll
    for (int jj = 0; jj < 16; jj++) {
        int dcol = jj * 8 + tq * 2;
        size_t a0 = ((size_t)(b * Sdim + sg0)) * Hdim + h * 128 + dcol;
        size_t a1 = ((size_t)(b * Sdim + sg0 + 8)) * Hdim + h * 128 + dcol;
        *(__half2*)(g_ctxh + a0) = __floats2half2_rn(o_acc[jj][0] * inv0, o_acc[jj][1] * inv0);
        *(__half2*)(g_ctxh + a1) = __floats2half2_rn(o_acc[jj][2] * inv1, o_acc[jj][3] * inv1);
    }
}

// ============================ mask passthrough ============================
__global__ void mask_kernel(const unsigned char* __restrict__ m, float* __restrict__ o, int n) {
    int i = blockIdx.x * blockDim.x + threadIdx.x;
    if (i < n) o[i] = m[i] ? 1.0f : 0.0f;
}

// ============================ launch ============================
extern "C" void kernel_launch(void* const* d_in, const int* in_sizes, int n_in,
                              void* d_out, int out_size) {
    const float* hs            = (const float*)d_in[0];
    const unsigned char* mask  = (const unsigned char*)d_in[1];
    const float* ln1w          = (const float*)d_in[2];
    const float* ln1b          = (const float*)d_in[3];
    const float* wqkv          = (const float*)d_in[4];
    const float* bqkv          = (const float*)d_in[5];
    const float* wdense        = (const float*)d_in[6];
    const float* bdense        = (const float*)d_in[7];
    const float* ln2w          = (const float*)d_in[8];
    const float* ln2b          = (const float*)d_in[9];
    const float* w1            = (const float*)d_in[10];
    const float* b1            = (const float*)d_in[11];
    const float* w2            = (const float*)d_in[12];
    const float* b2            = (const float*)d_in[13];
    float* out = (float*)d_out;

    float *phid;
    __half *pxh, *pctxh, *pinterh, *pqh, *pkh, *pvt, *pwqkvh, *pwdh, *pw1h, *pw2h;
    cudaGetSymbolAddress((void**)&phid,   g_hidden);
    cudaGetSymbolAddress((void**)&pxh,    g_xh);
    cudaGetSymbolAddress((void**)&pctxh,  g_ctxh);
    cudaGetSymbolAddress((void**)&pinterh, g_interh);
    cudaGetSymbolAddress((void**)&pqh,    g_qh);
    cudaGetSymbolAddress((void**)&pkh,    g_kh);
    cudaGetSymbolAddress((void**)&pvt,    g_vt);
    cudaGetSymbolAddress((void**)&pwqkvh, g_wqkvh);
    cudaGetSymbolAddress((void**)&pwdh,   g_wdh);
    cudaGetSymbolAddress((void**)&pw1h,   g_w1h);
    cudaGetSymbolAddress((void**)&pw2h,   g_w2h);

    cudaFuncSetAttribute(attn_kernel, cudaFuncAttributeMaxDynamicSharedMemorySize, AT_SMEM);
    cudaFuncSetAttribute(hgemm<1>, cudaFuncAttributeMaxDynamicSharedMemorySize, HM_SMEM);
    cudaFuncSetAttribute(hgemm<2>, cudaFuncAttributeMaxDynamicSharedMemorySize, HM_SMEM);
    cudaFuncSetAttribute(hgemm<4>, cudaFuncAttributeMaxDynamicSharedMemorySize, HM_SMEM);

    // weight prep: fp32 -> fp16 (vectorized)
    cvt_kernel<<<(3*Hdim*Hdim/8 + 255)/256, 256>>>(wqkv, pwqkvh, 3*Hdim*Hdim/8);
    cvt_kernel<<<(Hdim*Hdim/8   + 255)/256, 256>>>(wdense, pwdh, Hdim*Hdim/8);
    cvt_kernel<<<(FFdim*Hdim/8  + 255)/256, 256>>>(w1,     pw1h, FFdim*Hdim/8);
    cvt_kernel<<<(Hdim*FFdim/8  + 255)/256, 256>>>(w2,     pw2h, Hdim*FFdim/8);
    // LN1 -> xh
    ln_kernel<<<Mrows, 256>>>(hs, ln1w, ln1b, pxh);
    // RoPE trig table
    rope_table_kernel<<<(Sdim * 64) / 256, 256>>>();
    // QKV GEMM, fused epilogue: rope-split q/k -> qh/kh, transpose v -> vt
    hgemm<4><<<dim3(3 * Hdim / GBN, Mrows / GBM), 512, HM_SMEM>>>(
        pxh, pwqkvh, bqkv, nullptr, nullptr, pqh, pkh, pvt, Mrows, 3 * Hdim, Hdim);
    // HMMA flash attention (Bc=128) -> ctxh
    attn_kernel<<<dim3(Sdim / 128, Bdim * NHdim), 256, AT_SMEM>>>();
    // dense + residual(hidden_states) -> g_hidden (fp32)
    hgemm<2><<<dim3(Hdim / GBN, Mrows / GBM), 512, HM_SMEM>>>(
        pctxh, pwdh, bdense, hs, phid, nullptr, nullptr, nullptr, Mrows, Hdim, Hdim);
    // LN2 -> xh
    ln_kernel<<<Mrows, 256>>>(phid, ln2w, ln2b, pxh);
    // FF1 + GELU -> interh (fp16)
    hgemm<1><<<dim3(FFdim / GBN, Mrows / GBM), 512, HM_SMEM>>>(
        pxh, pw1h, b1, nullptr, nullptr, pinterh, nullptr, nullptr, Mrows, FFdim, Hdim);
    // FF2 + residual(g_hidden) -> out
    hgemm<2><<<dim3(Hdim / GBN, Mrows / GBM), 512, HM_SMEM>>>(
        pinterh, pw2h, b2, phid, out, nullptr, nullptr, nullptr, Mrows, Hdim, FFdim);
    // if output also carries the attention mask, convert it after hidden
    long long hid_elems = (long long)Mrows * Hdim;           // 8388608
    long long mask_elems = (long long)Sdim * Sdim;           // 4194304
    if ((long long)out_size >= hid_elems + mask_elems) {
        mask_kernel<<<(int)(mask_elems / 256), 256>>>(mask, out + hid_elems, (int)mask_elems);
    }
}

// round 15
// speedup vs baseline: 1.0232x; 1.0232x over previous
#include <cuda_runtime.h>
#include <cuda_fp16.h>
#include <cstdint>
#include <stdint.h>
#include <math.h>

// Problem constants
#define Bdim 2
#define Sdim 2048
#define Hdim 2048
#define NHdim 16
#define Ddim 128
#define FFdim 8192
#define Mrows (Bdim*Sdim)   // 4096

// -------- scratch (device globals; no allocation) --------
__device__ float g_hidden[(size_t)Mrows*Hdim];   // residual+attn_out
__device__ float g_cos[Sdim*64];
__device__ float g_sin[Sdim*64];
__device__ __half g_qkvh[(size_t)Mrows*3*Hdim];  // QKV gemm out (half)
__device__ __half g_qh[(size_t)Mrows*Hdim];      // [B,NH,S,D]
__device__ __half g_kh[(size_t)Mrows*Hdim];
__device__ __half g_vt[(size_t)Mrows*Hdim];      // [B,NH,D,S]
__device__ __half g_xh[(size_t)Mrows*Hdim];
__device__ __half g_ctxh[(size_t)Mrows*Hdim];
__device__ __half g_interh[(size_t)Mrows*FFdim];
__device__ __half g_wqkvh[(size_t)3*Hdim*Hdim];
__device__ __half g_wdh[(size_t)Hdim*Hdim];
__device__ __half g_w1h[(size_t)FFdim*Hdim];
__device__ __half g_w2h[(size_t)Hdim*FFdim];

// ============================ helpers ============================
__device__ __forceinline__ uint32_t smem_u32(const void* p) {
    uint32_t a;
    asm("{ .reg .u64 t; cvta.to.shared.u64 t, %1; cvt.u32.u64 %0, t; }" : "=r"(a) : "l"(p));
    return a;
}
__device__ __forceinline__ void ldsm4(uint32_t* r, uint32_t addr) {
    asm volatile("ldmatrix.sync.aligned.m8n8.x4.shared.b16 {%0,%1,%2,%3}, [%4];"
        : "=r"(r[0]), "=r"(r[1]), "=r"(r[2]), "=r"(r[3]) : "r"(addr));
}
__device__ __forceinline__ void mma16816(float* c, const uint32_t* a, uint32_t b0, uint32_t b1) {
    asm("mma.sync.aligned.m16n8k16.row.col.f32.f16.f16.f32 "
        "{%0,%1,%2,%3}, {%4,%5,%6,%7}, {%8,%9}, {%0,%1,%2,%3};"
        : "+f"(c[0]), "+f"(c[1]), "+f"(c[2]), "+f"(c[3])
        : "r"(a[0]), "r"(a[1]), "r"(a[2]), "r"(a[3]), "r"(b0), "r"(b1));
}
__device__ __forceinline__ void cp16(uint32_t dst, const void* src) {
    asm volatile("cp.async.cg.shared.global [%0], [%1], 16;"
        :: "r"(dst), "l"(__cvta_generic_to_global(src)) : "memory");
}
#define CP_COMMIT() asm volatile("cp.async.commit_group;" ::: "memory")
#define CP_WAIT(n)  asm volatile("cp.async.wait_group %0;" :: "n"(n) : "memory")

__device__ __forceinline__ float ex2(float x) {
    float r;
    asm("ex2.approx.ftz.f32 %0, %1;" : "=f"(r) : "f"(x));
    return r;
}
__device__ __forceinline__ uint32_t f22u(float a, float b) {
    __half2 h = __floats2half2_rn(a, b);
    return *(uint32_t*)&h;
}

// swizzled smem offset: rows of 64B (32 halfs), 16B chunk XOR (row>>1)&3
__device__ __forceinline__ uint32_t swoff(int row, int chunk) {
    return (uint32_t)(row * 64 + ((chunk ^ ((row >> 1) & 3)) << 4));
}

// ============================ consolidated prep kernel ============================
// blocks [0,6144): wqkv cvt | [6144,8192): wdense | [8192,16384): w1 | [16384,24576): w2
// blocks [24576,25088): rope table
__device__ __forceinline__ void cvt8(const float* in, __half* hi, size_t i) {
    float4 a = ((const float4*)in)[i * 2];
    float4 b = ((const float4*)in)[i * 2 + 1];
    __half2 h0 = __floats2half2_rn(a.x, a.y), h1 = __floats2half2_rn(a.z, a.w);
    __half2 h2 = __floats2half2_rn(b.x, b.y), h3 = __floats2half2_rn(b.z, b.w);
    ((uint4*)hi)[i] = make_uint4(*(uint32_t*)&h0, *(uint32_t*)&h1,
                                 *(uint32_t*)&h2, *(uint32_t*)&h3);
}
__global__ void prep_kernel(const float* __restrict__ wqkv, const float* __restrict__ wdense,
                            const float* __restrict__ w1, const float* __restrict__ w2) {
    int b = blockIdx.x, t = threadIdx.x;
    if (b < 6144) {
        cvt8(wqkv, g_wqkvh, (size_t)b * 256 + t);
    } else if (b < 8192) {
        cvt8(wdense, g_wdh, (size_t)(b - 6144) * 256 + t);
    } else if (b < 16384) {
        cvt8(w1, g_w1h, (size_t)(b - 8192) * 256 + t);
    } else if (b < 24576) {
        cvt8(w2, g_w2h, (size_t)(b - 16384) * 256 + t);
    } else {
        int idx = (b - 24576) * 256 + t;     // < Sdim*64
        int s = idx >> 6, i = idx & 63;
        double invf = exp(-(double)i * (9.210340371976184 / 64.0)); // ln(10000)/64
        double th = (double)s * invf;
        g_cos[idx] = (float)cos(th);
        g_sin[idx] = (float)sin(th);
    }
}

// ============================ HMMA GEMM (fp32 acc, 256x128 tile) ============================
// EPI: 1 = bias+GELU -> Ch half ; 2 = bias+residual -> C fp32 ; 3 = bias -> Ch half
#define GBM 256
#define GBN 128
#define NSTAGE 3
#define STAGE1 24576     // Ah 16K | Wh 8K
#define HM_SMEM (NSTAGE*STAGE1)

template<int EPI>
__global__ void __launch_bounds__(512, 1) hgemm(
    const __half* __restrict__ Ah_, const __half* __restrict__ Wh_,
    const float* __restrict__ bias, const float* __restrict__ res,
    float* __restrict__ C, __half* __restrict__ Ch,
    int M, int N, int K)
{
    extern __shared__ char sm[];
    uint32_t smb = smem_u32(sm);
    int tid = threadIdx.x;
    int lane = tid & 31, wid = tid >> 5;
    int wm = (wid & 3) * 64;
    int wn = (wid >> 2) * 32;
    int bm = blockIdx.y * GBM, bn = blockIdx.x * GBN;

    int aidx = tid * 2;
    int arow = aidx >> 2, ach = aidx & 3;
    int wrow = tid >> 2, wch = tid & 3;
    const __half* pAh = Ah_ + (size_t)(bm + arow) * K + ach * 8;
    const __half* pWh = Wh_ + (size_t)(bn + wrow) * K + wch * 8;
    uint32_t dA0 = swoff(arow, ach), dA1 = swoff(arow, ach + 1);
    uint32_t dW  = swoff(wrow, wch);

    float acc[4][4][4];
#pragma unroll
    for (int i = 0; i < 4; i++)
#pragma unroll
        for (int j = 0; j < 4; j++)
#pragma unroll
            for (int q = 0; q < 4; q++) acc[i][j][q] = 0.f;

    int mat = lane >> 3, mr = lane & 7;
    int fr_row = (mat & 1) * 8 + mr;
    int fr_ch  = mat >> 1;

    const int NC = K >> 5;

    auto load_stage = [&](int c) {
        uint32_t base = smb + (uint32_t)(c % NSTAGE) * STAGE1;
        size_t ko = (size_t)c * 32;
        cp16(base + 0     + dA0, pAh + ko);
        cp16(base + 0     + dA1, pAh + ko + 8);
        cp16(base + 16384 + dW,  pWh + ko);
    };

#pragma unroll
    for (int c = 0; c < NSTAGE - 1; c++) { load_stage(c); CP_COMMIT(); }

    for (int c = 0; c < NC; c++) {
        CP_WAIT(NSTAGE - 2);
        __syncthreads();
        if (c + NSTAGE - 1 < NC) { load_stage(c + NSTAGE - 1); }
        CP_COMMIT();

        uint32_t base = smb + (uint32_t)(c % NSTAGE) * STAGE1;
#pragma unroll
        for (int kk = 0; kk < 2; kk++) {
            uint32_t ah[4][4], bh[2][4];
#pragma unroll
            for (int i = 0; i < 4; i++) {
                uint32_t off = swoff(wm + i * 16 + fr_row, kk * 2 + fr_ch);
                ldsm4(ah[i], base + 0 + off);
            }
#pragma unroll
            for (int g = 0; g < 2; g++) {
                uint32_t off = swoff(wn + g * 16 + fr_row, kk * 2 + fr_ch);
                ldsm4(bh[g], base + 16384 + off);
            }
#pragma unroll
            for (int i = 0; i < 4; i++) {
#pragma unroll
                for (int jj = 0; jj < 4; jj++) {
                    int g = jj >> 1, h = jj & 1;
                    mma16816(acc[i][jj], ah[i], bh[g][h], bh[g][h+2]);
                }
            }
        }
    }

    int tr = lane >> 2;
    int tc = (lane & 3) * 2;
#pragma unroll
    for (int i = 0; i < 4; i++) {
#pragma unroll
        for (int jj = 0; jj < 4; jj++) {
            int n0 = bn + wn + jj * 8 + tc;
            float b0 = bias[n0], b1 = bias[n0 + 1];
#pragma unroll
            for (int half = 0; half < 2; half++) {
                int m = bm + wm + i * 16 + tr + half * 8;
                size_t idx = (size_t)m * N + n0;
                float v0 = acc[i][jj][half * 2 + 0] + b0;
                float v1 = acc[i][jj][half * 2 + 1] + b1;
                if (EPI == 1) {
                    v0 = 0.5f * v0 * (1.0f + erff(v0 * 0.70710678118654752f));
                    v1 = 0.5f * v1 * (1.0f + erff(v1 * 0.70710678118654752f));
                    *(__half2*)(Ch + idx) = __floats2half2_rn(v0, v1);
                } else if (EPI == 3) {
                    *(__half2*)(Ch + idx) = __floats2half2_rn(v0, v1);
                } else {
                    if (EPI == 2) { v0 += res[idx]; v1 += res[idx + 1]; }
                    *(float2*)(C + idx) = make_float2(v0, v1);
                }
            }
        }
    }
}

// ============================ LayerNorm -> fp16 (float4) ============================
__global__ void ln_kernel(const float* __restrict__ in, const float* __restrict__ w,
                          const float* __restrict__ b, __half* __restrict__ oh) {
    __shared__ float2 red[256];
    int row = blockIdx.x;
    const float* x = in + (size_t)row * Hdim;
    float s = 0.f, ss = 0.f;
#pragma unroll
    for (int it = 0; it < 2; it++) {
        int i = (threadIdx.x + it * 256) * 4;
        float4 v = *(const float4*)(x + i);
        s += v.x + v.y + v.z + v.w;
        ss = fmaf(v.x, v.x, fmaf(v.y, v.y, fmaf(v.z, v.z, fmaf(v.w, v.w, ss))));
    }
    red[threadIdx.x] = make_float2(s, ss);
    __syncthreads();
    for (int o = 128; o > 0; o >>= 1) {
        if (threadIdx.x < o) {
            float2 a = red[threadIdx.x], c = red[threadIdx.x + o];
            red[threadIdx.x] = make_float2(a.x + c.x, a.y + c.y);
        }
        __syncthreads();
    }
    float mean = red[0].x * (1.0f / Hdim);
    float var  = red[0].y * (1.0f / Hdim) - mean * mean;
    float rstd = rsqrtf(var + 1e-5f);
#pragma unroll
    for (int it = 0; it < 2; it++) {
        int i = (threadIdx.x + it * 256) * 4;
        float4 v = *(const float4*)(x + i);
        float4 wv = *(const float4*)(w + i);
        float4 bv = *(const float4*)(b + i);
        __half2 h0 = __floats2half2_rn((v.x - mean) * rstd * wv.x + bv.x,
                                       (v.y - mean) * rstd * wv.y + bv.y);
        __half2 h1 = __floats2half2_rn((v.z - mean) * rstd * wv.z + bv.z,
                                       (v.w - mean) * rstd * wv.w + bv.w);
        *(uint2*)(oh + (size_t)row * Hdim + i) = make_uint2(*(uint32_t*)&h0, *(uint32_t*)&h1);
    }
}

// ============================ QKV split + RoPE (q,k only; half in/out) ============================
__global__ void rope_kernel() {
    int row = blockIdx.x;      // b*S + s
    int h = blockIdx.y;
    int d = threadIdx.x;       // 0..127
    int s = row & (Sdim - 1);
    int b = row >> 11;
    const __half* src = g_qkvh + (size_t)row * (3 * Hdim) + h * (3 * Ddim);
    float q = __half2float(src[d]);
    float k = __half2float(src[Ddim + d]);
    int di = d & 63;
    float cs = g_cos[s * 64 + di];
    float sn = g_sin[s * 64 + di];
    float qp, kp;
    if (d < 64) { qp = -__half2float(src[d + 64]);      kp = -__half2float(src[Ddim + d + 64]); }
    else        { qp =  __half2float(src[d - 64]);      kp =  __half2float(src[Ddim + d - 64]); }
    size_t oidx = ((size_t)(b * NHdim + h) * Sdim + s) * Ddim + d;
    g_qh[oidx] = __float2half(q * cs + qp * sn);
    g_kh[oidx] = __float2half(k * cs + kp * sn);
}

// ============================ V transpose: qkvh -> [bh,D,S] ============================
__global__ void vt_kernel() {
    __shared__ __half tile[64][66];
    int bh = blockIdx.z;
    int b = bh >> 4, h = bh & 15;
    int s0 = blockIdx.x * 64, d0 = blockIdx.y * 64;
    const __half* src = g_qkvh + (size_t)(b * Sdim + s0) * (3 * Hdim) + h * (3 * Ddim) + 2 * Ddim + d0;
#pragma unroll
    for (int i = 0; i < 16; i++) {
        int idx = threadIdx.x + i * 256;
        int r = idx >> 6, c = idx & 63;
        tile[r][c] = src[(size_t)r * (3 * Hdim) + c];
    }
    __syncthreads();
    __half* dst = g_vt + ((size_t)bh * Ddim + d0) * Sdim + s0;
#pragma unroll
    for (int i = 0; i < 16; i++) {
        int idx = threadIdx.x + i * 256;
        int dr = idx >> 6, sc = idx & 63;
        dst[(size_t)dr * Sdim + sc] = tile[sc][dr];
    }
}

// ============================ HMMA flash attention (causal, Bc=128) ============================
#define AT_STAGE 65536
#define AT_SMEM (32768 + 2*AT_STAGE)

__global__ void __launch_bounds__(256, 1) attn_kernel() {
    extern __shared__ char sm[];
    uint32_t smb = smem_u32(sm);
    uint32_t qbase = smb;
    int tid = threadIdx.x;
    int lane = tid & 31, wid = tid >> 5;
    int qt = gridDim.x - 1 - blockIdx.x;
    int bh = blockIdx.y;

    const __half* Qg  = g_qh + ((size_t)bh * Sdim + (size_t)qt * 128) * Ddim;
    const __half* Kg  = g_kh + (size_t)bh * Sdim * Ddim;
    const __half* VTg = g_vt + (size_t)bh * Ddim * Sdim;

    {
        int row = tid >> 1, kb0 = (tid & 1) * 2;
#pragma unroll
        for (int i = 0; i < 8; i++) {
            int kb = kb0 + (i >> 2), ch = i & 3;
            cp16(qbase + kb * 8192 + swoff(row, ch), Qg + (size_t)row * 128 + kb * 32 + ch * 8);
        }
    }
    auto load_stage = [&](int kt) {
        uint32_t st = smb + 32768 + (uint32_t)(kt & 1) * AT_STAGE;
        const __half* kp = Kg + (size_t)kt * 128 * 128;
#pragma unroll
        for (int i = 0; i < 8; i++) {
            int idx = tid + i * 256;
            int krow = idx >> 4, kb = (idx >> 2) & 3, ch = idx & 3;
            cp16(st + kb * 8192 + swoff(krow, ch), kp + (size_t)krow * 128 + kb * 32 + ch * 8);
        }
        const __half* vp = VTg + (size_t)kt * 128;
#pragma unroll
        for (int i = 0; i < 8; i++) {
            int idx = tid + i * 256;
            int vs = idx >> 9, drow = (idx >> 2) & 127, ch = idx & 3;
            cp16(st + 32768 + vs * 8192 + swoff(drow, ch),
                 vp + (size_t)drow * Sdim + vs * 32 + ch * 8);
        }
    };

    int nkt = qt + 1;
    load_stage(0); CP_COMMIT();
    load_stage(1); CP_COMMIT();
    CP_WAIT(1);
    __syncthreads();

    int mat = lane >> 3, mr = lane & 7;
    int fr_row = (mat & 1) * 8 + mr, fr_ch = mat >> 1;
    int wm = wid * 16;
    int tr = lane >> 2, tq = lane & 3;

    uint32_t qf[8][4];
#pragma unroll
    for (int kk = 0; kk < 8; kk++)
        ldsm4(qf[kk], qbase + (kk >> 1) * 8192 + swoff(wm + fr_row, (kk & 1) * 2 + fr_ch));

    float o_acc[16][4];
#pragma unroll
    for (int j = 0; j < 16; j++)
#pragma unroll
        for (int q = 0; q < 4; q++) o_acc[j][q] = 0.f;
    float m_run[2] = { -INFINITY, -INFINITY };
    float l_run[2] = { 0.f, 0.f };

    const float SC = 0.08838834764831845f * 1.4426950408889634f;
    int rowg0 = qt * 128 + wm + tr;

    for (int kt = 0; kt < nkt; kt++) {
        if (kt > 0) { CP_WAIT(1); __syncthreads(); }
        uint32_t st = smb + 32768 + (uint32_t)(kt & 1) * AT_STAGE;

        float s_acc[16][4];
#pragma unroll
        for (int j = 0; j < 16; j++)
#pragma unroll
            for (int q = 0; q < 4; q++) s_acc[j][q] = 0.f;
#pragma unroll
        for (int kk = 0; kk < 8; kk++) {
#pragma unroll
            for (int g = 0; g < 8; g++) {
                uint32_t kf[4];
                ldsm4(kf, st + (kk >> 1) * 8192 + swoff(16 * g + fr_row, (kk & 1) * 2 + fr_ch));
                mma16816(s_acc[2 * g + 0], qf[kk], kf[0], kf[2]);
                mma16816(s_acc[2 * g + 1], qf[kk], kf[1], kf[3]);
            }
        }

#pragma unroll
        for (int j = 0; j < 16; j++)
#pragma unroll
            for (int q = 0; q < 4; q++) {
                int colg = kt * 128 + j * 8 + tq * 2 + (q & 1);
                int rowg = rowg0 + (q >> 1) * 8;
                float x = s_acc[j][q] * SC;
                s_acc[j][q] = (colg <= rowg) ? x : -1e30f;
            }
        float mrow0 = -1e30f, mrow1 = -1e30f;
#pragma unroll
        for (int j = 0; j < 16; j++) {
            mrow0 = fmaxf(mrow0, fmaxf(s_acc[j][0], s_acc[j][1]));
            mrow1 = fmaxf(mrow1, fmaxf(s_acc[j][2], s_acc[j][3]));
        }
        mrow0 = fmaxf(mrow0, __shfl_xor_sync(0xFFFFFFFF, mrow0, 1));
        mrow0 = fmaxf(mrow0, __shfl_xor_sync(0xFFFFFFFF, mrow0, 2));
        mrow1 = fmaxf(mrow1, __shfl_xor_sync(0xFFFFFFFF, mrow1, 1));
        mrow1 = fmaxf(mrow1, __shfl_xor_sync(0xFFFFFFFF, mrow1, 2));
        float mnew0 = fmaxf(m_run[0], mrow0);
        float mnew1 = fmaxf(m_run[1], mrow1);
        float alpha0 = ex2(m_run[0] - mnew0);
        float alpha1 = ex2(m_run[1] - mnew1);
        float rs0 = 0.f, rs1 = 0.f;
#pragma unroll
        for (int j = 0; j < 16; j++) {
            s_acc[j][0] = ex2(s_acc[j][0] - mnew0);
            s_acc[j][1] = ex2(s_acc[j][1] - mnew0);
            s_acc[j][2] = ex2(s_acc[j][2] - mnew1);
            s_acc[j][3] = ex2(s_acc[j][3] - mnew1);
            rs0 += s_acc[j][0] + s_acc[j][1];
            rs1 += s_acc[j][2] + s_acc[j][3];
        }
        rs0 += __shfl_xor_sync(0xFFFFFFFF, rs0, 1);
        rs0 += __shfl_xor_sync(0xFFFFFFFF, rs0, 2);
        rs1 += __shfl_xor_sync(0xFFFFFFFF, rs1, 1);
        rs1 += __shfl_xor_sync(0xFFFFFFFF, rs1, 2);
        l_run[0] = l_run[0] * alpha0 + rs0;
        l_run[1] = l_run[1] * alpha1 + rs1;
        m_run[0] = mnew0;
        m_run[1] = mnew1;
#pragma unroll
        for (int jj = 0; jj < 16; jj++) {
            o_acc[jj][0] *= alpha0; o_acc[jj][1] *= alpha0;
            o_acc[jj][2] *= alpha1; o_acc[jj][3] *= alpha1;
        }

        uint32_t pa[4][2][4];
#pragma unroll
        for (int vs = 0; vs < 4; vs++)
#pragma unroll
            for (int t = 0; t < 2; t++) {
                int j0 = vs * 4 + 2 * t;
                pa[vs][t][0] = f22u(s_acc[j0][0],   s_acc[j0][1]);
                pa[vs][t][1] = f22u(s_acc[j0][2],   s_acc[j0][3]);
                pa[vs][t][2] = f22u(s_acc[j0+1][0], s_acc[j0+1][1]);
                pa[vs][t][3] = f22u(s_acc[j0+1][2], s_acc[j0+1][3]);
            }

#pragma unroll
        for (int vs = 0; vs < 4; vs++) {
#pragma unroll
            for (int g = 0; g < 8; g++) {
#pragma unroll
                for (int t = 0; t < 2; t++) {
                    uint32_t vb[4];
                    ldsm4(vb, st + 32768 + vs * 8192 + swoff(16 * g + fr_row, t * 2 + fr_ch));
                    mma16816(o_acc[2 * g + 0], pa[vs][t], vb[0], vb[2]);
                    mma16816(o_acc[2 * g + 1], pa[vs][t], vb[1], vb[3]);
                }
            }
        }

        if (kt + 2 < nkt) {
            __syncthreads();
            load_stage(kt + 2);
            CP_COMMIT();
        } else {
            CP_COMMIT();
        }
    }

    float inv0 = 1.0f / l_run[0];
    float inv1 = 1.0f / l_run[1];
    int b = bh >> 4, h = bh & 15;
    int sg0 = qt * 128 + wm + tr;
#pragma unroll
    for (int jj = 0; jj < 16; jj++) {
        int dcol = jj * 8 + tq * 2;
        size_t a0 = ((size_t)(b * Sdim + sg0)) * Hdim + h * 128 + dcol;
        size_t a1 = ((size_t)(b * Sdim + sg0 + 8)) * Hdim + h * 128 + dcol;
        *(__half2*)(g_ctxh + a0) = __floats2half2_rn(o_acc[jj][0] * inv0, o_acc[jj][1] * inv0);
        *(__half2*)(g_ctxh + a1) = __floats2half2_rn(o_acc[jj][2] * inv1, o_acc[jj][3] * inv1);
    }
}

// ============================ mask passthrough ============================
__global__ void mask_kernel(const unsigned char* __restrict__ m, float* __restrict__ o, int n) {
    int i = blockIdx.x * blockDim.x + threadIdx.x;
    if (i < n) o[i] = m[i] ? 1.0f : 0.0f;
}

// ============================ launch ============================
extern "C" void kernel_launch(void* const* d_in, const int* in_sizes, int n_in,
                              void* d_out, int out_size) {
    const float* hs            = (const float*)d_in[0];
    const unsigned char* mask  = (const unsigned char*)d_in[1];
    const float* ln1w          = (const float*)d_in[2];
    const float* ln1b          = (const float*)d_in[3];
    const float* wqkv          = (const float*)d_in[4];
    const float* bqkv          = (const float*)d_in[5];
    const float* wdense        = (const float*)d_in[6];
    const float* bdense        = (const float*)d_in[7];
    const float* ln2w          = (const float*)d_in[8];
    const float* ln2b          = (const float*)d_in[9];
    const float* w1            = (const float*)d_in[10];
    const float* b1            = (const float*)d_in[11];
    const float* w2            = (const float*)d_in[12];
    const float* b2            = (const float*)d_in[13];
    float* out = (float*)d_out;

    float *phid;
    __half *pxh, *pctxh, *pinterh, *pqkvh, *pwqkvh, *pwdh, *pw1h, *pw2h;
    cudaGetSymbolAddress((void**)&phid,   g_hidden);
    cudaGetSymbolAddress((void**)&pxh,    g_xh);
    cudaGetSymbolAddress((void**)&pctxh,  g_ctxh);
    cudaGetSymbolAddress((void**)&pinterh, g_interh);
    cudaGetSymbolAddress((void**)&pqkvh,  g_qkvh);
    cudaGetSymbolAddress((void**)&pwqkvh, g_wqkvh);
    cudaGetSymbolAddress((void**)&pwdh,   g_wdh);
    cudaGetSymbolAddress((void**)&pw1h,   g_w1h);
    cudaGetSymbolAddress((void**)&pw2h,   g_w2h);

    cudaFuncSetAttribute(attn_kernel, cudaFuncAttributeMaxDynamicSharedMemorySize, AT_SMEM);
    cudaFuncSetAttribute(hgemm<1>, cudaFuncAttributeMaxDynamicSharedMemorySize, HM_SMEM);
    cudaFuncSetAttribute(hgemm<2>, cudaFuncAttributeMaxDynamicSharedMemorySize, HM_SMEM);
    cudaFuncSetAttribute(hgemm<3>, cudaFuncAttributeMaxDynamicSharedMemorySize, HM_SMEM);

    // consolidated prep: all 4 weight cvts + rope table in one launch
    prep_kernel<<<25088, 256>>>(wqkv, wdense, w1, w2);
    // LN1 -> xh
    ln_kernel<<<Mrows, 256>>>(hs, ln1w, ln1b, pxh);
    // QKV = x @ wqkv^T + bqkv (half out, fp32 acc)
    hgemm<3><<<dim3(3 * Hdim / GBN, Mrows / GBM), 512, HM_SMEM>>>(
        pxh, pwqkvh, bqkv, nullptr, nullptr, pqkvh, Mrows, 3 * Hdim, Hdim);
    // split + rope -> qh/kh (half, [B,NH,S,D])
    rope_kernel<<<dim3(Mrows, NHdim), 128>>>();
    // V transpose (direct from qkvh) -> vt (half, [B,NH,D,S])
    vt_kernel<<<dim3(Sdim / 64, Ddim / 64, Bdim * NHdim), 256>>>();
    // HMMA flash attention (Bc=128) -> ctxh
    attn_kernel<<<dim3(Sdim / 128, Bdim * NHdim), 256, AT_SMEM>>>();
    // dense + residual(hidden_states) -> g_hidden (fp32)
    hgemm<2><<<dim3(Hdim / GBN, Mrows / GBM), 512, HM_SMEM>>>(
        pctxh, pwdh, bdense, hs, phid, nullptr, Mrows, Hdim, Hdim);
    // LN2 -> xh
    ln_kernel<<<Mrows, 256>>>(phid, ln2w, ln2b, pxh);
    // FF1 + GELU -> interh (fp16)
    hgemm<1><<<dim3(FFdim / GBN, Mrows / GBM), 512, HM_SMEM>>>(
        pxh, pw1h, b1, nullptr, nullptr, pinterh, Mrows, FFdim, Hdim);
    // FF2 + residual(g_hidden) -> out
    hgemm<2><<<dim3(Hdim / GBN, Mrows / GBM), 512, HM_SMEM>>>(
        pinterh, pw2h, b2, phid, out, nullptr, Mrows, Hdim, FFdim);
    // if output also carries the attention mask, convert it after hidden
    long long hid_elems = (long long)Mrows * Hdim;           // 8388608
    long long mask_elems = (long long)Sdim * Sdim;           // 4194304
    if ((long long)out_size >= hid_elems + mask_elems) {
        mask_kernel<<<(int)(mask_elems / 256), 256>>>(mask, out + hid_elems, (int)mask_elems);
    }
}

// round 16
// speedup vs baseline: 1.0376x; 1.0141x over previous
#include <cuda_runtime.h>
#include <cuda_fp16.h>
#include <cstdint>
#include <stdint.h>
#include <math.h>

// Problem constants
#define Bdim 2
#define Sdim 2048
#define Hdim 2048
#define NHdim 16
#define Ddim 128
#define FFdim 8192
#define Mrows (Bdim*Sdim)   // 4096

// -------- scratch (device globals; no allocation) --------
__device__ float g_hidden[(size_t)Mrows*Hdim];   // residual+attn_out
__device__ float g_cos[Sdim*64];
__device__ float g_sin[Sdim*64];
__device__ __half g_qkvh[(size_t)Mrows*3*Hdim];  // QKV gemm out (half)
__device__ __half g_qh[(size_t)Mrows*Hdim];      // [B,NH,S,D]
__device__ __half g_kh[(size_t)Mrows*Hdim];
__device__ __half g_vt[(size_t)Mrows*Hdim];      // [B,NH,D,S]
__device__ __half g_xh[(size_t)Mrows*Hdim];
__device__ __half g_ctxh[(size_t)Mrows*Hdim];
__device__ __half g_interh[(size_t)Mrows*FFdim];
__device__ __half g_wqkvh[(size_t)3*Hdim*Hdim];
__device__ __half g_wdh[(size_t)Hdim*Hdim];
__device__ __half g_w1h[(size_t)FFdim*Hdim];
__device__ __half g_w2h[(size_t)Hdim*FFdim];

// ============================ helpers ============================
__device__ __forceinline__ uint32_t smem_u32(const void* p) {
    uint32_t a;
    asm("{ .reg .u64 t; cvta.to.shared.u64 t, %1; cvt.u32.u64 %0, t; }" : "=r"(a) : "l"(p));
    return a;
}
__device__ __forceinline__ void ldsm4(uint32_t* r, uint32_t addr) {
    asm volatile("ldmatrix.sync.aligned.m8n8.x4.shared.b16 {%0,%1,%2,%3}, [%4];"
        : "=r"(r[0]), "=r"(r[1]), "=r"(r[2]), "=r"(r[3]) : "r"(addr));
}
__device__ __forceinline__ void mma16816(float* c, const uint32_t* a, uint32_t b0, uint32_t b1) {
    asm("mma.sync.aligned.m16n8k16.row.col.f32.f16.f16.f32 "
        "{%0,%1,%2,%3}, {%4,%5,%6,%7}, {%8,%9}, {%0,%1,%2,%3};"
        : "+f"(c[0]), "+f"(c[1]), "+f"(c[2]), "+f"(c[3])
        : "r"(a[0]), "r"(a[1]), "r"(a[2]), "r"(a[3]), "r"(b0), "r"(b1));
}
__device__ __forceinline__ void cp16(uint32_t dst, const void* src) {
    asm volatile("cp.async.cg.shared.global [%0], [%1], 16;"
        :: "r"(dst), "l"(__cvta_generic_to_global(src)) : "memory");
}
#define CP_COMMIT() asm volatile("cp.async.commit_group;" ::: "memory")
#define CP_WAIT(n)  asm volatile("cp.async.wait_group %0;" :: "n"(n) : "memory")

__device__ __forceinline__ float ex2(float x) {
    float r;
    asm("ex2.approx.ftz.f32 %0, %1;" : "=f"(r) : "f"(x));
    return r;
}
__device__ __forceinline__ uint32_t f22u(float a, float b) {
    __half2 h = __floats2half2_rn(a, b);
    return *(uint32_t*)&h;
}

// swizzled smem offset: rows of 64B (32 halfs), 16B chunk XOR (row>>1)&3
__device__ __forceinline__ uint32_t swoff(int row, int chunk) {
    return (uint32_t)(row * 64 + ((chunk ^ ((row >> 1) & 3)) << 4));
}

// ============================ consolidated prep kernel ============================
__device__ __forceinline__ void cvt8(const float* in, __half* hi, size_t i) {
    float4 a = ((const float4*)in)[i * 2];
    float4 b = ((const float4*)in)[i * 2 + 1];
    __half2 h0 = __floats2half2_rn(a.x, a.y), h1 = __floats2half2_rn(a.z, a.w);
    __half2 h2 = __floats2half2_rn(b.x, b.y), h3 = __floats2half2_rn(b.z, b.w);
    ((uint4*)hi)[i] = make_uint4(*(uint32_t*)&h0, *(uint32_t*)&h1,
                                 *(uint32_t*)&h2, *(uint32_t*)&h3);
}
__global__ void prep_kernel(const float* __restrict__ wqkv, const float* __restrict__ wdense,
                            const float* __restrict__ w1, const float* __restrict__ w2) {
    int b = blockIdx.x, t = threadIdx.x;
    if (b < 6144) {
        cvt8(wqkv, g_wqkvh, (size_t)b * 256 + t);
    } else if (b < 8192) {
        cvt8(wdense, g_wdh, (size_t)(b - 6144) * 256 + t);
    } else if (b < 16384) {
        cvt8(w1, g_w1h, (size_t)(b - 8192) * 256 + t);
    } else if (b < 24576) {
        cvt8(w2, g_w2h, (size_t)(b - 16384) * 256 + t);
    } else {
        int idx = (b - 24576) * 256 + t;     // < Sdim*64
        int s = idx >> 6, i = idx & 63;
        double invf = exp(-(double)i * (9.210340371976184 / 64.0)); // ln(10000)/64
        double th = (double)s * invf;
        g_cos[idx] = (float)cos(th);
        g_sin[idx] = (float)sin(th);
    }
}

// ============================ HMMA GEMM (fp32 acc, 256x128 tile) ============================
// EPI: 1 = bias+GELU -> Ch half ; 2 = bias+residual -> C fp32 ; 3 = bias -> Ch half
#define GBM 256
#define GBN 128
#define NSTAGE 3
#define STAGE1 24576     // Ah 16K | Wh 8K
#define HM_SMEM (NSTAGE*STAGE1)

template<int EPI>
__global__ void __launch_bounds__(512, 1) hgemm(
    const __half* __restrict__ Ah_, const __half* __restrict__ Wh_,
    const float* __restrict__ bias, const float* __restrict__ res,
    float* __restrict__ C, __half* __restrict__ Ch,
    int M, int N, int K)
{
    extern __shared__ char sm[];
    uint32_t smb = smem_u32(sm);
    int tid = threadIdx.x;
    int lane = tid & 31, wid = tid >> 5;
    int wm = (wid & 3) * 64;
    int wn = (wid >> 2) * 32;
    int bm = blockIdx.y * GBM, bn = blockIdx.x * GBN;

    int aidx = tid * 2;
    int arow = aidx >> 2, ach = aidx & 3;
    int wrow = tid >> 2, wch = tid & 3;
    const __half* pAh = Ah_ + (size_t)(bm + arow) * K + ach * 8;
    const __half* pWh = Wh_ + (size_t)(bn + wrow) * K + wch * 8;
    uint32_t dA0 = swoff(arow, ach), dA1 = swoff(arow, ach + 1);
    uint32_t dW  = swoff(wrow, wch);

    float acc[4][4][4];
#pragma unroll
    for (int i = 0; i < 4; i++)
#pragma unroll
        for (int j = 0; j < 4; j++)
#pragma unroll
            for (int q = 0; q < 4; q++) acc[i][j][q] = 0.f;

    int mat = lane >> 3, mr = lane & 7;
    int fr_row = (mat & 1) * 8 + mr;
    int fr_ch  = mat >> 1;

    const int NC = K >> 5;

    auto load_stage = [&](int c) {
        uint32_t base = smb + (uint32_t)(c % NSTAGE) * STAGE1;
        size_t ko = (size_t)c * 32;
        cp16(base + 0     + dA0, pAh + ko);
        cp16(base + 0     + dA1, pAh + ko + 8);
        cp16(base + 16384 + dW,  pWh + ko);
    };

#pragma unroll
    for (int c = 0; c < NSTAGE - 1; c++) { load_stage(c); CP_COMMIT(); }

    for (int c = 0; c < NC; c++) {
        CP_WAIT(NSTAGE - 2);
        __syncthreads();
        if (c + NSTAGE - 1 < NC) { load_stage(c + NSTAGE - 1); }
        CP_COMMIT();

        uint32_t base = smb + (uint32_t)(c % NSTAGE) * STAGE1;
#pragma unroll
        for (int kk = 0; kk < 2; kk++) {
            uint32_t ah[4][4], bh[2][4];
#pragma unroll
            for (int i = 0; i < 4; i++) {
                uint32_t off = swoff(wm + i * 16 + fr_row, kk * 2 + fr_ch);
                ldsm4(ah[i], base + 0 + off);
            }
#pragma unroll
            for (int g = 0; g < 2; g++) {
                uint32_t off = swoff(wn + g * 16 + fr_row, kk * 2 + fr_ch);
                ldsm4(bh[g], base + 16384 + off);
            }
#pragma unroll
            for (int i = 0; i < 4; i++) {
#pragma unroll
                for (int jj = 0; jj < 4; jj++) {
                    int g = jj >> 1, h = jj & 1;
                    mma16816(acc[i][jj], ah[i], bh[g][h], bh[g][h+2]);
                }
            }
        }
    }

    int tr = lane >> 2;
    int tc = (lane & 3) * 2;
#pragma unroll
    for (int i = 0; i < 4; i++) {
#pragma unroll
        for (int jj = 0; jj < 4; jj++) {
            int n0 = bn + wn + jj * 8 + tc;
            float b0 = bias[n0], b1 = bias[n0 + 1];
#pragma unroll
            for (int half = 0; half < 2; half++) {
                int m = bm + wm + i * 16 + tr + half * 8;
                size_t idx = (size_t)m * N + n0;
                float v0 = acc[i][jj][half * 2 + 0] + b0;
                float v1 = acc[i][jj][half * 2 + 1] + b1;
                if (EPI == 1) {
                    v0 = 0.5f * v0 * (1.0f + erff(v0 * 0.70710678118654752f));
                    v1 = 0.5f * v1 * (1.0f + erff(v1 * 0.70710678118654752f));
                    *(__half2*)(Ch + idx) = __floats2half2_rn(v0, v1);
                } else if (EPI == 3) {
                    *(__half2*)(Ch + idx) = __floats2half2_rn(v0, v1);
                } else {
                    if (EPI == 2) { v0 += res[idx]; v1 += res[idx + 1]; }
                    *(float2*)(C + idx) = make_float2(v0, v1);
                }
            }
        }
    }
}

// ============================ LayerNorm -> fp16 (float4) ============================
__global__ void ln_kernel(const float* __restrict__ in, const float* __restrict__ w,
                          const float* __restrict__ b, __half* __restrict__ oh) {
    __shared__ float2 red[256];
    int row = blockIdx.x;
    const float* x = in + (size_t)row * Hdim;
    float s = 0.f, ss = 0.f;
#pragma unroll
    for (int it = 0; it < 2; it++) {
        int i = (threadIdx.x + it * 256) * 4;
        float4 v = *(const float4*)(x + i);
        s += v.x + v.y + v.z + v.w;
        ss = fmaf(v.x, v.x, fmaf(v.y, v.y, fmaf(v.z, v.z, fmaf(v.w, v.w, ss))));
    }
    red[threadIdx.x] = make_float2(s, ss);
    __syncthreads();
    for (int o = 128; o > 0; o >>= 1) {
        if (threadIdx.x < o) {
            float2 a = red[threadIdx.x], c = red[threadIdx.x + o];
            red[threadIdx.x] = make_float2(a.x + c.x, a.y + c.y);
        }
        __syncthreads();
    }
    float mean = red[0].x * (1.0f / Hdim);
    float var  = red[0].y * (1.0f / Hdim) - mean * mean;
    float rstd = rsqrtf(var + 1e-5f);
#pragma unroll
    for (int it = 0; it < 2; it++) {
        int i = (threadIdx.x + it * 256) * 4;
        float4 v = *(const float4*)(x + i);
        float4 wv = *(const float4*)(w + i);
        float4 bv = *(const float4*)(b + i);
        __half2 h0 = __floats2half2_rn((v.x - mean) * rstd * wv.x + bv.x,
                                       (v.y - mean) * rstd * wv.y + bv.y);
        __half2 h1 = __floats2half2_rn((v.z - mean) * rstd * wv.z + bv.z,
                                       (v.w - mean) * rstd * wv.w + bv.w);
        *(uint2*)(oh + (size_t)row * Hdim + i) = make_uint2(*(uint32_t*)&h0, *(uint32_t*)&h1);
    }
}

// ============================ fused rope + V transpose (vectorized) ============================
// blocks [0,16384): rope — 4 units/(256-thr block), unit = (row,h), 64 thr/unit (half2 per thread)
// blocks [16384,18432): vt — same tiling as old vt_kernel, half2 vectorized
__global__ void rv_kernel() {
    __shared__ __half tile[64][66];
    int blk = blockIdx.x, t = threadIdx.x;
    if (blk < 16384) {
        int u = blk * 4 + (t >> 6);        // unit = row*16 + h
        int row = u >> 4, h = u & 15;
        int d2 = t & 63, d = d2 * 2;
        int s = row & (Sdim - 1), b = row >> 11;
        const __half2* src = (const __half2*)(g_qkvh + (size_t)row * (3 * Hdim) + h * (3 * Ddim));
        __half2 qv = src[d2];
        __half2 kv = src[64 + d2];
        int pd2 = d2 ^ 32;                 // partner (d^64)/2
        float2 qf  = __half22float2(qv);
        float2 kf  = __half22float2(kv);
        float2 qpf = __half22float2(src[pd2]);
        float2 kpf = __half22float2(src[64 + pd2]);
        float sgn = (d < 64) ? -1.f : 1.f;
        int di = d & 63;
        float2 cs = *(const float2*)(g_cos + s * 64 + di);
        float2 sn = *(const float2*)(g_sin + s * 64 + di);
        size_t ob = (((size_t)(b * NHdim + h)) * Sdim + s) * Ddim + d;
        *(__half2*)(g_qh + ob) = __floats2half2_rn(
            qf.x * cs.x + sgn * qpf.x * sn.x, qf.y * cs.y + sgn * qpf.y * sn.y);
        *(__half2*)(g_kh + ob) = __floats2half2_rn(
            kf.x * cs.x + sgn * kpf.x * sn.x, kf.y * cs.y + sgn * kpf.y * sn.y);
    } else {
        int v = blk - 16384;               // [0, 2048)
        int bh = v >> 6;
        int rest = v & 63;
        int dt = rest >> 5, st = rest & 31;
        int b = bh >> 4, h = bh & 15;
        int s0 = st * 64, d0 = dt * 64;
        const __half* src = g_qkvh + (size_t)(b * Sdim + s0) * (3 * Hdim)
                            + h * (3 * Ddim) + 2 * Ddim + d0;
        // load 64x64 tile as half2 (32 half2 per row)
#pragma unroll
        for (int i = 0; i < 8; i++) {
            int idx2 = t + i * 256;
            int r = idx2 >> 5, c2 = idx2 & 31;
            *(__half2*)&tile[r][c2 * 2] = *(const __half2*)(src + (size_t)r * (3 * Hdim) + c2 * 2);
        }
        __syncthreads();
        __half* dst = g_vt + ((size_t)bh * Ddim + d0) * Sdim + s0;
#pragma unroll
        for (int i = 0; i < 8; i++) {
            int idx2 = t + i * 256;
            int dr = idx2 >> 5, sc = (idx2 & 31) * 2;
            __half2 hv = __halves2half2(tile[sc][dr], tile[sc + 1][dr]);
            *(__half2*)(dst + (size_t)dr * Sdim + sc) = hv;
        }
    }
}

// ============================ HMMA flash attention (causal, Bc=128) ============================
#define AT_STAGE 65536
#define AT_SMEM (32768 + 2*AT_STAGE)

__global__ void __launch_bounds__(256, 1) attn_kernel() {
    extern __shared__ char sm[];
    uint32_t smb = smem_u32(sm);
    uint32_t qbase = smb;
    int tid = threadIdx.x;
    int lane = tid & 31, wid = tid >> 5;
    int qt = gridDim.x - 1 - blockIdx.x;
    int bh = blockIdx.y;

    const __half* Qg  = g_qh + ((size_t)bh * Sdim + (size_t)qt * 128) * Ddim;
    const __half* Kg  = g_kh + (size_t)bh * Sdim * Ddim;
    const __half* VTg = g_vt + (size_t)bh * Ddim * Sdim;

    {
        int row = tid >> 1, kb0 = (tid & 1) * 2;
#pragma unroll
        for (int i = 0; i < 8; i++) {
            int kb = kb0 + (i >> 2), ch = i & 3;
            cp16(qbase + kb * 8192 + swoff(row, ch), Qg + (size_t)row * 128 + kb * 32 + ch * 8);
        }
    }
    auto load_stage = [&](int kt) {
        uint32_t st = smb + 32768 + (uint32_t)(kt & 1) * AT_STAGE;
        const __half* kp = Kg + (size_t)kt * 128 * 128;
#pragma unroll
        for (int i = 0; i < 8; i++) {
            int idx = tid + i * 256;
            int krow = idx >> 4, kb = (idx >> 2) & 3, ch = idx & 3;
            cp16(st + kb * 8192 + swoff(krow, ch), kp + (size_t)krow * 128 + kb * 32 + ch * 8);
        }
        const __half* vp = VTg + (size_t)kt * 128;
#pragma unroll
        for (int i = 0; i < 8; i++) {
            int idx = tid + i * 256;
            int vs = idx >> 9, drow = (idx >> 2) & 127, ch = idx & 3;
            cp16(st + 32768 + vs * 8192 + swoff(drow, ch),
                 vp + (size_t)drow * Sdim + vs * 32 + ch * 8);
        }
    };

    int nkt = qt + 1;
    load_stage(0); CP_COMMIT();
    load_stage(1); CP_COMMIT();
    CP_WAIT(1);
    __syncthreads();

    int mat = lane >> 3, mr = lane & 7;
    int fr_row = (mat & 1) * 8 + mr, fr_ch = mat >> 1;
    int wm = wid * 16;
    int tr = lane >> 2, tq = lane & 3;

    uint32_t qf[8][4];
#pragma unroll
    for (int kk = 0; kk < 8; kk++)
        ldsm4(qf[kk], qbase + (kk >> 1) * 8192 + swoff(wm + fr_row, (kk & 1) * 2 + fr_ch));

    float o_acc[16][4];
#pragma unroll
    for (int j = 0; j < 16; j++)
#pragma unroll
        for (int q = 0; q < 4; q++) o_acc[j][q] = 0.f;
    float m_run[2] = { -INFINITY, -INFINITY };
    float l_run[2] = { 0.f, 0.f };

    const float SC = 0.08838834764831845f * 1.4426950408889634f;
    int rowg0 = qt * 128 + wm + tr;

    for (int kt = 0; kt < nkt; kt++) {
        if (kt > 0) { CP_WAIT(1); __syncthreads(); }
        uint32_t st = smb + 32768 + (uint32_t)(kt & 1) * AT_STAGE;

        float s_acc[16][4];
#pragma unroll
        for (int j = 0; j < 16; j++)
#pragma unroll
            for (int q = 0; q < 4; q++) s_acc[j][q] = 0.f;
#pragma unroll
        for (int kk = 0; kk < 8; kk++) {
#pragma unroll
            for (int g = 0; g < 8; g++) {
                uint32_t kf[4];
                ldsm4(kf, st + (kk >> 1) * 8192 + swoff(16 * g + fr_row, (kk & 1) * 2 + fr_ch));
                mma16816(s_acc[2 * g + 0], qf[kk], kf[0], kf[2]);
                mma16816(s_acc[2 * g + 1], qf[kk], kf[1], kf[3]);
            }
        }

#pragma unroll
        for (int j = 0; j < 16; j++)
#pragma unroll
            for (int q = 0; q < 4; q++) {
                int colg = kt * 128 + j * 8 + tq * 2 + (q & 1);
                int rowg = rowg0 + (q >> 1) * 8;
                float x = s_acc[j][q] * SC;
                s_acc[j][q] = (colg <= rowg) ? x : -1e30f;
            }
        float mrow0 = -1e30f, mrow1 = -1e30f;
#pragma unroll
        for (int j = 0; j < 16; j++) {
            mrow0 = fmaxf(mrow0, fmaxf(s_acc[j][0], s_acc[j][1]));
            mrow1 = fmaxf(mrow1, fmaxf(s_acc[j][2], s_acc[j][3]));
        }
        mrow0 = fmaxf(mrow0, __shfl_xor_sync(0xFFFFFFFF, mrow0, 1));
        mrow0 = fmaxf(mrow0, __shfl_xor_sync(0xFFFFFFFF, mrow0, 2));
        mrow1 = fmaxf(mrow1, __shfl_xor_sync(0xFFFFFFFF, mrow1, 1));
        mrow1 = fmaxf(mrow1, __shfl_xor_sync(0xFFFFFFFF, mrow1, 2));
        float mnew0 = fmaxf(m_run[0], mrow0);
        float mnew1 = fmaxf(m_run[1], mrow1);
        float alpha0 = ex2(m_run[0] - mnew0);
        float alpha1 = ex2(m_run[1] - mnew1);
        float rs0 = 0.f, rs1 = 0.f;
#pragma unroll
        for (int j = 0; j < 16; j++) {
            s_acc[j][0] = ex2(s_acc[j][0] - mnew0);
            s_acc[j][1] = ex2(s_acc[j][1] - mnew0);
            s_acc[j][2] = ex2(s_acc[j][2] - mnew1);
            s_acc[j][3] = ex2(s_acc[j][3] - mnew1);
            rs0 += s_acc[j][0] + s_acc[j][1];
            rs1 += s_acc[j][2] + s_acc[j][3];
        }
        rs0 += __shfl_xor_sync(0xFFFFFFFF, rs0, 1);
        rs0 += __shfl_xor_sync(0xFFFFFFFF, rs0, 2);
        rs1 += __shfl_xor_sync(0xFFFFFFFF, rs1, 1);
        rs1 += __shfl_xor_sync(0xFFFFFFFF, rs1, 2);
        l_run[0] = l_run[0] * alpha0 + rs0;
        l_run[1] = l_run[1] * alpha1 + rs1;
        m_run[0] = mnew0;
        m_run[1] = mnew1;
#pragma unroll
        for (int jj = 0; jj < 16; jj++) {
            o_acc[jj][0] *= alpha0; o_acc[jj][1] *= alpha0;
            o_acc[jj][2] *= alpha1; o_acc[jj][3] *= alpha1;
        }

        uint32_t pa[4][2][4];
#pragma unroll
        for (int vs = 0; vs < 4; vs++)
#pragma unroll
            for (int t = 0; t < 2; t++) {
                int j0 = vs * 4 + 2 * t;
                pa[vs][t][0] = f22u(s_acc[j0][0],   s_acc[j0][1]);
                pa[vs][t][1] = f22u(s_acc[j0][2],   s_acc[j0][3]);
                pa[vs][t][2] = f22u(s_acc[j0+1][0], s_acc[j0+1][1]);
                pa[vs][t][3] = f22u(s_acc[j0+1][2], s_acc[j0+1][3]);
            }

#pragma unroll
        for (int vs = 0; vs < 4; vs++) {
#pragma unroll
            for (int g = 0; g < 8; g++) {
#pragma unroll
                for (int t = 0; t < 2; t++) {
                    uint32_t vb[4];
                    ldsm4(vb, st + 32768 + vs * 8192 + swoff(16 * g + fr_row, t * 2 + fr_ch));
                    mma16816(o_acc[2 * g + 0], pa[vs][t], vb[0], vb[2]);
                    mma16816(o_acc[2 * g + 1], pa[vs][t], vb[1], vb[3]);
                }
            }
        }

        if (kt + 2 < nkt) {
            __syncthreads();
            load_stage(kt + 2);
            CP_COMMIT();
        } else {
            CP_COMMIT();
        }
    }

    float inv0 = 1.0f / l_run[0];
    float inv1 = 1.0f / l_run[1];
    int b = bh >> 4, h = bh & 15;
    int sg0 = qt * 128 + wm + tr;
#pragma unroll
    for (int jj = 0; jj < 16; jj++) {
        int dcol = jj * 8 + tq * 2;
        size_t a0 = ((size_t)(b * Sdim + sg0)) * Hdim + h * 128 + dcol;
        size_t a1 = ((size_t)(b * Sdim + sg0 + 8)) * Hdim + h * 128 + dcol;
        *(__half2*)(g_ctxh + a0) = __floats2half2_rn(o_acc[jj][0] * inv0, o_acc[jj][1] * inv0);
        *(__half2*)(g_ctxh + a1) = __floats2half2_rn(o_acc[jj][2] * inv1, o_acc[jj][3] * inv1);
    }
}

// ============================ mask passthrough ============================
__global__ void mask_kernel(const unsigned char* __restrict__ m, float* __restrict__ o, int n) {
    int i = blockIdx.x * blockDim.x + threadIdx.x;
    if (i < n) o[i] = m[i] ? 1.0f : 0.0f;
}

// ============================ launch ============================
extern "C" void kernel_launch(void* const* d_in, const int* in_sizes, int n_in,
                              void* d_out, int out_size) {
    const float* hs            = (const float*)d_in[0];
    const unsigned char* mask  = (const unsigned char*)d_in[1];
    const float* ln1w          = (const float*)d_in[2];
    const float* ln1b          = (const float*)d_in[3];
    const float* wqkv          = (const float*)d_in[4];
    const float* bqkv          = (const float*)d_in[5];
    const float* wdense        = (const float*)d_in[6];
    const float* bdense        = (const float*)d_in[7];
    const float* ln2w          = (const float*)d_in[8];
    const float* ln2b          = (const float*)d_in[9];
    const float* w1            = (const float*)d_in[10];
    const float* b1            = (const float*)d_in[11];
    const float* w2            = (const float*)d_in[12];
    const float* b2            = (const float*)d_in[13];
    float* out = (float*)d_out;

    float *phid;
    __half *pxh, *pctxh, *pinterh, *pqkvh, *pwqkvh, *pwdh, *pw1h, *pw2h;
    cudaGetSymbolAddress((void**)&phid,   g_hidden);
    cudaGetSymbolAddress((void**)&pxh,    g_xh);
    cudaGetSymbolAddress((void**)&pctxh,  g_ctxh);
    cudaGetSymbolAddress((void**)&pinterh, g_interh);
    cudaGetSymbolAddress((void**)&pqkvh,  g_qkvh);
    cudaGetSymbolAddress((void**)&pwqkvh, g_wqkvh);
    cudaGetSymbolAddress((void**)&pwdh,   g_wdh);
    cudaGetSymbolAddress((void**)&pw1h,   g_w1h);
    cudaGetSymbolAddress((void**)&pw2h,   g_w2h);

    cudaFuncSetAttribute(attn_kernel, cudaFuncAttributeMaxDynamicSharedMemorySize, AT_SMEM);
    cudaFuncSetAttribute(hgemm<1>, cudaFuncAttributeMaxDynamicSharedMemorySize, HM_SMEM);
    cudaFuncSetAttribute(hgemm<2>, cudaFuncAttributeMaxDynamicSharedMemorySize, HM_SMEM);
    cudaFuncSetAttribute(hgemm<3>, cudaFuncAttributeMaxDynamicSharedMemorySize, HM_SMEM);

    // consolidated prep: all 4 weight cvts + rope table in one launch
    prep_kernel<<<25088, 256>>>(wqkv, wdense, w1, w2);
    // LN1 -> xh
    ln_kernel<<<Mrows, 256>>>(hs, ln1w, ln1b, pxh);
    // QKV = x @ wqkv^T + bqkv (half out, fp32 acc)
    hgemm<3><<<dim3(3 * Hdim / GBN, Mrows / GBM), 512, HM_SMEM>>>(
        pxh, pwqkvh, bqkv, nullptr, nullptr, pqkvh, Mrows, 3 * Hdim, Hdim);
    // fused rope (q,k) + V transpose
    rv_kernel<<<18432, 256>>>();
    // HMMA flash attention (Bc=128) -> ctxh
    attn_kernel<<<dim3(Sdim / 128, Bdim * NHdim), 256, AT_SMEM>>>();
    // dense + residual(hidden_states) -> g_hidden (fp32)
    hgemm<2><<<dim3(Hdim / GBN, Mrows / GBM), 512, HM_SMEM>>>(
        pctxh, pwdh, bdense, hs, phid, nullptr, Mrows, Hdim, Hdim);
    // LN2 -> xh
    ln_kernel<<<Mrows, 256>>>(phid, ln2w, ln2b, pxh);
    // FF1 + GELU -> interh (fp16)
    hgemm<1><<<dim3(FFdim / GBN, Mrows / GBM), 512, HM_SMEM>>>(
        pxh, pw1h, b1, nullptr, nullptr, pinterh, Mrows, FFdim, Hdim);
    // FF2 + residual(g_hidden) -> out
    hgemm<2><<<dim3(Hdim / GBN, Mrows / GBM), 512, HM_SMEM>>>(
        pinterh, pw2h, b2, phid, out, nullptr, Mrows, Hdim, FFdim);
    // if output also carries the attention mask, convert it after hidden
    long long hid_elems = (long long)Mrows * Hdim;           // 8388608
    long long mask_elems = (long long)Sdim * Sdim;           // 4194304
    if ((long long)out_size >= hid_elems + mask_elems) {
        mask_kernel<<<(int)(mask_elems / 256), 256>>>(mask, out + hid_elems, (int)mask_elems);
    }
}

// round 17
// speedup vs baseline: 1.0518x; 1.0137x over previous
#include <cuda_runtime.h>
#include <cuda_fp16.h>
#include <cstdint>
#include <stdint.h>
#include <math.h>

// Problem constants
#define Bdim 2
#define Sdim 2048
#define Hdim 2048
#define NHdim 16
#define Ddim 128
#define FFdim 8192
#define Mrows (Bdim*Sdim)   // 4096

// -------- scratch (device globals; no allocation) --------
__device__ float g_hidden[(size_t)Mrows*Hdim];   // residual+attn_out
__device__ float g_cos[Sdim*64];
__device__ float g_sin[Sdim*64];
__device__ __half g_qkvh[(size_t)Mrows*3*Hdim];  // QKV gemm out (half)
__device__ __half g_qh[(size_t)Mrows*Hdim];      // [B,NH,S,D]
__device__ __half g_kh[(size_t)Mrows*Hdim];
__device__ __half g_vt[(size_t)Mrows*Hdim];      // [B,NH,D,S]
__device__ __half g_xh[(size_t)Mrows*Hdim];
__device__ __half g_ctxh[(size_t)Mrows*Hdim];
__device__ __half g_interh[(size_t)Mrows*FFdim];
__device__ __half g_wqkvh[(size_t)3*Hdim*Hdim];
__device__ __half g_wdh[(size_t)Hdim*Hdim];
__device__ __half g_w1h[(size_t)FFdim*Hdim];
__device__ __half g_w2h[(size_t)Hdim*FFdim];

// ============================ helpers ============================
__device__ __forceinline__ uint32_t smem_u32(const void* p) {
    uint32_t a;
    asm("{ .reg .u64 t; cvta.to.shared.u64 t, %1; cvt.u32.u64 %0, t; }" : "=r"(a) : "l"(p));
    return a;
}
__device__ __forceinline__ void ldsm4(uint32_t* r, uint32_t addr) {
    asm volatile("ldmatrix.sync.aligned.m8n8.x4.shared.b16 {%0,%1,%2,%3}, [%4];"
        : "=r"(r[0]), "=r"(r[1]), "=r"(r[2]), "=r"(r[3]) : "r"(addr));
}
__device__ __forceinline__ void mma16816(float* c, const uint32_t* a, uint32_t b0, uint32_t b1) {
    asm("mma.sync.aligned.m16n8k16.row.col.f32.f16.f16.f32 "
        "{%0,%1,%2,%3}, {%4,%5,%6,%7}, {%8,%9}, {%0,%1,%2,%3};"
        : "+f"(c[0]), "+f"(c[1]), "+f"(c[2]), "+f"(c[3])
        : "r"(a[0]), "r"(a[1]), "r"(a[2]), "r"(a[3]), "r"(b0), "r"(b1));
}
__device__ __forceinline__ void cp16(uint32_t dst, const void* src) {
    asm volatile("cp.async.cg.shared.global [%0], [%1], 16;"
        :: "r"(dst), "l"(__cvta_generic_to_global(src)) : "memory");
}
#define CP_COMMIT() asm volatile("cp.async.commit_group;" ::: "memory")
#define CP_WAIT(n)  asm volatile("cp.async.wait_group %0;" :: "n"(n) : "memory")

__device__ __forceinline__ float ex2(float x) {
    float r;
    asm("ex2.approx.ftz.f32 %0, %1;" : "=f"(r) : "f"(x));
    return r;
}
__device__ __forceinline__ uint32_t f22u(float a, float b) {
    __half2 h = __floats2half2_rn(a, b);
    return *(uint32_t*)&h;
}

// swizzled smem offset: rows of 64B (32 halfs), 16B chunk XOR (row>>1)&3
__device__ __forceinline__ uint32_t swoff(int row, int chunk) {
    return (uint32_t)(row * 64 + ((chunk ^ ((row >> 1) & 3)) << 4));
}

// ============================ consolidated prep kernel ============================
// [0,6144): wqkv | [6144,8192): wdense | [8192,16384): w1 | [16384,24576): w2
// [24576,25088): rope table | [25088,29184): LN1 | [29184,...): mask (1024 elems/block)
__device__ __forceinline__ void cvt8(const float* in, __half* hi, size_t i) {
    float4 a = ((const float4*)in)[i * 2];
    float4 b = ((const float4*)in)[i * 2 + 1];
    __half2 h0 = __floats2half2_rn(a.x, a.y), h1 = __floats2half2_rn(a.z, a.w);
    __half2 h2 = __floats2half2_rn(b.x, b.y), h3 = __floats2half2_rn(b.z, b.w);
    ((uint4*)hi)[i] = make_uint4(*(uint32_t*)&h0, *(uint32_t*)&h1,
                                 *(uint32_t*)&h2, *(uint32_t*)&h3);
}
__global__ void prep_kernel(const float* __restrict__ wqkv, const float* __restrict__ wdense,
                            const float* __restrict__ w1, const float* __restrict__ w2,
                            const float* __restrict__ hs, const float* __restrict__ ln1w,
                            const float* __restrict__ ln1b,
                            const unsigned char* __restrict__ mask,
                            float* __restrict__ mask_out, int mask_elems) {
    __shared__ float2 red[256];
    int b = blockIdx.x, t = threadIdx.x;
    if (b < 6144) {
        cvt8(wqkv, g_wqkvh, (size_t)b * 256 + t);
    } else if (b < 8192) {
        cvt8(wdense, g_wdh, (size_t)(b - 6144) * 256 + t);
    } else if (b < 16384) {
        cvt8(w1, g_w1h, (size_t)(b - 8192) * 256 + t);
    } else if (b < 24576) {
        cvt8(w2, g_w2h, (size_t)(b - 16384) * 256 + t);
    } else if (b < 25088) {
        int idx = (b - 24576) * 256 + t;     // < Sdim*64
        int s = idx >> 6, i = idx & 63;
        double invf = exp(-(double)i * (9.210340371976184 / 64.0)); // ln(10000)/64
        double th = (double)s * invf;
        g_cos[idx] = (float)cos(th);
        g_sin[idx] = (float)sin(th);
    } else if (b < 29184) {
        // LN1 for row b-25088
        int row = b - 25088;
        const float* x = hs + (size_t)row * Hdim;
        float s = 0.f, ss = 0.f;
#pragma unroll
        for (int it = 0; it < 2; it++) {
            int i = (t + it * 256) * 4;
            float4 v = *(const float4*)(x + i);
            s += v.x + v.y + v.z + v.w;
            ss = fmaf(v.x, v.x, fmaf(v.y, v.y, fmaf(v.z, v.z, fmaf(v.w, v.w, ss))));
        }
        red[t] = make_float2(s, ss);
        __syncthreads();
        for (int o = 128; o > 0; o >>= 1) {
            if (t < o) {
                float2 a = red[t], c = red[t + o];
                red[t] = make_float2(a.x + c.x, a.y + c.y);
            }
            __syncthreads();
        }
        float mean = red[0].x * (1.0f / Hdim);
        float var  = red[0].y * (1.0f / Hdim) - mean * mean;
        float rstd = rsqrtf(var + 1e-5f);
#pragma unroll
        for (int it = 0; it < 2; it++) {
            int i = (t + it * 256) * 4;
            float4 v = *(const float4*)(x + i);
            float4 wv = *(const float4*)(ln1w + i);
            float4 bv = *(const float4*)(ln1b + i);
            __half2 h0 = __floats2half2_rn((v.x - mean) * rstd * wv.x + bv.x,
                                           (v.y - mean) * rstd * wv.y + bv.y);
            __half2 h1 = __floats2half2_rn((v.z - mean) * rstd * wv.z + bv.z,
                                           (v.w - mean) * rstd * wv.w + bv.w);
            *(uint2*)(g_xh + (size_t)row * Hdim + i) = make_uint2(*(uint32_t*)&h0, *(uint32_t*)&h1);
        }
    } else {
        int idx = ((b - 29184) * 256 + t) * 4;
        if (idx < mask_elems) {
            uchar4 m = *(const uchar4*)(mask + idx);
            float4 o = make_float4(m.x ? 1.f : 0.f, m.y ? 1.f : 0.f,
                                   m.z ? 1.f : 0.f, m.w ? 1.f : 0.f);
            *(float4*)(mask_out + idx) = o;
        }
    }
}

// ============================ HMMA GEMM (fp32 acc, 256x128 tile) ============================
// EPI: 1 = bias+GELU -> Ch half ; 2 = bias+residual -> C fp32 ; 3 = bias -> Ch half
#define GBM 256
#define GBN 128
#define NSTAGE 3
#define STAGE1 24576     // Ah 16K | Wh 8K
#define HM_SMEM (NSTAGE*STAGE1)

template<int EPI>
__global__ void __launch_bounds__(512, 1) hgemm(
    const __half* __restrict__ Ah_, const __half* __restrict__ Wh_,
    const float* __restrict__ bias, const float* __restrict__ res,
    float* __restrict__ C, __half* __restrict__ Ch,
    int M, int N, int K)
{
    extern __shared__ char sm[];
    uint32_t smb = smem_u32(sm);
    int tid = threadIdx.x;
    int lane = tid & 31, wid = tid >> 5;
    int wm = (wid & 3) * 64;
    int wn = (wid >> 2) * 32;
    int bm = blockIdx.y * GBM, bn = blockIdx.x * GBN;

    int aidx = tid * 2;
    int arow = aidx >> 2, ach = aidx & 3;
    int wrow = tid >> 2, wch = tid & 3;
    const __half* pAh = Ah_ + (size_t)(bm + arow) * K + ach * 8;
    const __half* pWh = Wh_ + (size_t)(bn + wrow) * K + wch * 8;
    uint32_t dA0 = swoff(arow, ach), dA1 = swoff(arow, ach + 1);
    uint32_t dW  = swoff(wrow, wch);

    float acc[4][4][4];
#pragma unroll
    for (int i = 0; i < 4; i++)
#pragma unroll
        for (int j = 0; j < 4; j++)
#pragma unroll
            for (int q = 0; q < 4; q++) acc[i][j][q] = 0.f;

    int mat = lane >> 3, mr = lane & 7;
    int fr_row = (mat & 1) * 8 + mr;
    int fr_ch  = mat >> 1;

    const int NC = K >> 5;

    auto load_stage = [&](int c) {
        uint32_t base = smb + (uint32_t)(c % NSTAGE) * STAGE1;
        size_t ko = (size_t)c * 32;
        cp16(base + 0     + dA0, pAh + ko);
        cp16(base + 0     + dA1, pAh + ko + 8);
        cp16(base + 16384 + dW,  pWh + ko);
    };

#pragma unroll
    for (int c = 0; c < NSTAGE - 1; c++) { load_stage(c); CP_COMMIT(); }

    for (int c = 0; c < NC; c++) {
        CP_WAIT(NSTAGE - 2);
        __syncthreads();
        if (c + NSTAGE - 1 < NC) { load_stage(c + NSTAGE - 1); }
        CP_COMMIT();

        uint32_t base = smb + (uint32_t)(c % NSTAGE) * STAGE1;
#pragma unroll
        for (int kk = 0; kk < 2; kk++) {
            uint32_t ah[4][4], bh[2][4];
#pragma unroll
            for (int i = 0; i < 4; i++) {
                uint32_t off = swoff(wm + i * 16 + fr_row, kk * 2 + fr_ch);
                ldsm4(ah[i], base + 0 + off);
            }
#pragma unroll
            for (int g = 0; g < 2; g++) {
                uint32_t off = swoff(wn + g * 16 + fr_row, kk * 2 + fr_ch);
                ldsm4(bh[g], base + 16384 + off);
            }
#pragma unroll
            for (int i = 0; i < 4; i++) {
#pragma unroll
                for (int jj = 0; jj < 4; jj++) {
                    int g = jj >> 1, h = jj & 1;
                    mma16816(acc[i][jj], ah[i], bh[g][h], bh[g][h+2]);
                }
            }
        }
    }

    int tr = lane >> 2;
    int tc = (lane & 3) * 2;
#pragma unroll
    for (int i = 0; i < 4; i++) {
#pragma unroll
        for (int jj = 0; jj < 4; jj++) {
            int n0 = bn + wn + jj * 8 + tc;
            float b0 = bias[n0], b1 = bias[n0 + 1];
#pragma unroll
            for (int half = 0; half < 2; half++) {
                int m = bm + wm + i * 16 + tr + half * 8;
                size_t idx = (size_t)m * N + n0;
                float v0 = acc[i][jj][half * 2 + 0] + b0;
                float v1 = acc[i][jj][half * 2 + 1] + b1;
                if (EPI == 1) {
                    v0 = 0.5f * v0 * (1.0f + erff(v0 * 0.70710678118654752f));
                    v1 = 0.5f * v1 * (1.0f + erff(v1 * 0.70710678118654752f));
                    *(__half2*)(Ch + idx) = __floats2half2_rn(v0, v1);
                } else if (EPI == 3) {
                    *(__half2*)(Ch + idx) = __floats2half2_rn(v0, v1);
                } else {
                    if (EPI == 2) { v0 += res[idx]; v1 += res[idx + 1]; }
                    *(float2*)(C + idx) = make_float2(v0, v1);
                }
            }
        }
    }
}

// ============================ LayerNorm -> fp16 (float4) ============================
__global__ void ln_kernel(const float* __restrict__ in, const float* __restrict__ w,
                          const float* __restrict__ b, __half* __restrict__ oh) {
    __shared__ float2 red[256];
    int row = blockIdx.x;
    const float* x = in + (size_t)row * Hdim;
    float s = 0.f, ss = 0.f;
#pragma unroll
    for (int it = 0; it < 2; it++) {
        int i = (threadIdx.x + it * 256) * 4;
        float4 v = *(const float4*)(x + i);
        s += v.x + v.y + v.z + v.w;
        ss = fmaf(v.x, v.x, fmaf(v.y, v.y, fmaf(v.z, v.z, fmaf(v.w, v.w, ss))));
    }
    red[threadIdx.x] = make_float2(s, ss);
    __syncthreads();
    for (int o = 128; o > 0; o >>= 1) {
        if (threadIdx.x < o) {
            float2 a = red[threadIdx.x], c = red[threadIdx.x + o];
            red[threadIdx.x] = make_float2(a.x + c.x, a.y + c.y);
        }
        __syncthreads();
    }
    float mean = red[0].x * (1.0f / Hdim);
    float var  = red[0].y * (1.0f / Hdim) - mean * mean;
    float rstd = rsqrtf(var + 1e-5f);
#pragma unroll
    for (int it = 0; it < 2; it++) {
        int i = (threadIdx.x + it * 256) * 4;
        float4 v = *(const float4*)(x + i);
        float4 wv = *(const float4*)(w + i);
        float4 bv = *(const float4*)(b + i);
        __half2 h0 = __floats2half2_rn((v.x - mean) * rstd * wv.x + bv.x,
                                       (v.y - mean) * rstd * wv.y + bv.y);
        __half2 h1 = __floats2half2_rn((v.z - mean) * rstd * wv.z + bv.z,
                                       (v.w - mean) * rstd * wv.w + bv.w);
        *(uint2*)(oh + (size_t)row * Hdim + i) = make_uint2(*(uint32_t*)&h0, *(uint32_t*)&h1);
    }
}

// ============================ fused rope + V transpose (vectorized) ============================
__global__ void rv_kernel() {
    __shared__ __half tile[64][66];
    int blk = blockIdx.x, t = threadIdx.x;
    if (blk < 16384) {
        int u = blk * 4 + (t >> 6);        // unit = row*16 + h
        int row = u >> 4, h = u & 15;
        int d2 = t & 63, d = d2 * 2;
        int s = row & (Sdim - 1), b = row >> 11;
        const __half2* src = (const __half2*)(g_qkvh + (size_t)row * (3 * Hdim) + h * (3 * Ddim));
        __half2 qv = src[d2];
        __half2 kv = src[64 + d2];
        int pd2 = d2 ^ 32;                 // partner (d^64)/2
        float2 qf  = __half22float2(qv);
        float2 kf  = __half22float2(kv);
        float2 qpf = __half22float2(src[pd2]);
        float2 kpf = __half22float2(src[64 + pd2]);
        float sgn = (d < 64) ? -1.f : 1.f;
        int di = d & 63;
        float2 cs = *(const float2*)(g_cos + s * 64 + di);
        float2 sn = *(const float2*)(g_sin + s * 64 + di);
        size_t ob = (((size_t)(b * NHdim + h)) * Sdim + s) * Ddim + d;
        *(__half2*)(g_qh + ob) = __floats2half2_rn(
            qf.x * cs.x + sgn * qpf.x * sn.x, qf.y * cs.y + sgn * qpf.y * sn.y);
        *(__half2*)(g_kh + ob) = __floats2half2_rn(
            kf.x * cs.x + sgn * kpf.x * sn.x, kf.y * cs.y + sgn * kpf.y * sn.y);
    } else {
        int v = blk - 16384;               // [0, 2048)
        int bh = v >> 6;
        int rest = v & 63;
        int dt = rest >> 5, st = rest & 31;
        int b = bh >> 4, h = bh & 15;
        int s0 = st * 64, d0 = dt * 64;
        const __half* src = g_qkvh + (size_t)(b * Sdim + s0) * (3 * Hdim)
                            + h * (3 * Ddim) + 2 * Ddim + d0;
#pragma unroll
        for (int i = 0; i < 8; i++) {
            int idx2 = t + i * 256;
            int r = idx2 >> 5, c2 = idx2 & 31;
            *(__half2*)&tile[r][c2 * 2] = *(const __half2*)(src + (size_t)r * (3 * Hdim) + c2 * 2);
        }
        __syncthreads();
        __half* dst = g_vt + ((size_t)bh * Ddim + d0) * Sdim + s0;
#pragma unroll
        for (int i = 0; i < 8; i++) {
            int idx2 = t + i * 256;
            int dr = idx2 >> 5, sc = (idx2 & 31) * 2;
            __half2 hv = __halves2half2(tile[sc][dr], tile[sc + 1][dr]);
            *(__half2*)(dst + (size_t)dr * Sdim + sc) = hv;
        }
    }
}

// ============================ HMMA flash attention (causal, Bc=128) ============================
#define AT_STAGE 65536
#define AT_SMEM (32768 + 2*AT_STAGE)

__global__ void __launch_bounds__(256, 1) attn_kernel() {
    extern __shared__ char sm[];
    uint32_t smb = smem_u32(sm);
    uint32_t qbase = smb;
    int tid = threadIdx.x;
    int lane = tid & 31, wid = tid >> 5;
    int qt = gridDim.x - 1 - blockIdx.x;
    int bh = blockIdx.y;

    const __half* Qg  = g_qh + ((size_t)bh * Sdim + (size_t)qt * 128) * Ddim;
    const __half* Kg  = g_kh + (size_t)bh * Sdim * Ddim;
    const __half* VTg = g_vt + (size_t)bh * Ddim * Sdim;

    {
        int row = tid >> 1, kb0 = (tid & 1) * 2;
#pragma unroll
        for (int i = 0; i < 8; i++) {
            int kb = kb0 + (i >> 2), ch = i & 3;
            cp16(qbase + kb * 8192 + swoff(row, ch), Qg + (size_t)row * 128 + kb * 32 + ch * 8);
        }
    }
    auto load_stage = [&](int kt) {
        uint32_t st = smb + 32768 + (uint32_t)(kt & 1) * AT_STAGE;
        const __half* kp = Kg + (size_t)kt * 128 * 128;
#pragma unroll
        for (int i = 0; i < 8; i++) {
            int idx = tid + i * 256;
            int krow = idx >> 4, kb = (idx >> 2) & 3, ch = idx & 3;
            cp16(st + kb * 8192 + swoff(krow, ch), kp + (size_t)krow * 128 + kb * 32 + ch * 8);
        }
        const __half* vp = VTg + (size_t)kt * 128;
#pragma unroll
        for (int i = 0; i < 8; i++) {
            int idx = tid + i * 256;
            int vs = idx >> 9, drow = (idx >> 2) & 127, ch = idx & 3;
            cp16(st + 32768 + vs * 8192 + swoff(drow, ch),
                 vp + (size_t)drow * Sdim + vs * 32 + ch * 8);
        }
    };

    int nkt = qt + 1;
    load_stage(0); CP_COMMIT();
    load_stage(1); CP_COMMIT();
    CP_WAIT(1);
    __syncthreads();

    int mat = lane >> 3, mr = lane & 7;
    int fr_row = (mat & 1) * 8 + mr, fr_ch = mat >> 1;
    int wm = wid * 16;
    int tr = lane >> 2, tq = lane & 3;

    uint32_t qf[8][4];
#pragma unroll
    for (int kk = 0; kk < 8; kk++)
        ldsm4(qf[kk], qbase + (kk >> 1) * 8192 + swoff(wm + fr_row, (kk & 1) * 2 + fr_ch));

    float o_acc[16][4];
#pragma unroll
    for (int j = 0; j < 16; j++)
#pragma unroll
        for (int q = 0; q < 4; q++) o_acc[j][q] = 0.f;
    float m_run[2] = { -INFINITY, -INFINITY };
    float l_run[2] = { 0.f, 0.f };

    const float SC = 0.08838834764831845f * 1.4426950408889634f;
    int rowg0 = qt * 128 + wm + tr;

    for (int kt = 0; kt < nkt; kt++) {
        if (kt > 0) { CP_WAIT(1); __syncthreads(); }
        uint32_t st = smb + 32768 + (uint32_t)(kt & 1) * AT_STAGE;

        float s_acc[16][4];
#pragma unroll
        for (int j = 0; j < 16; j++)
#pragma unroll
            for (int q = 0; q < 4; q++) s_acc[j][q] = 0.f;
#pragma unroll
        for (int kk = 0; kk < 8; kk++) {
#pragma unroll
            for (int g = 0; g < 8; g++) {
                uint32_t kf[4];
                ldsm4(kf, st + (kk >> 1) * 8192 + swoff(16 * g + fr_row, (kk & 1) * 2 + fr_ch));
                mma16816(s_acc[2 * g + 0], qf[kk], kf[0], kf[2]);
                mma16816(s_acc[2 * g + 1], qf[kk], kf[1], kf[3]);
            }
        }

#pragma unroll
        for (int j = 0; j < 16; j++)
#pragma unroll
            for (int q = 0; q < 4; q++) {
                int colg = kt * 128 + j * 8 + tq * 2 + (q & 1);
                int rowg = rowg0 + (q >> 1) * 8;
                float x = s_acc[j][q] * SC;
                s_acc[j][q] = (colg <= rowg) ? x : -1e30f;
            }
        float mrow0 = -1e30f, mrow1 = -1e30f;
#pragma unroll
        for (int j = 0; j < 16; j++) {
            mrow0 = fmaxf(mrow0, fmaxf(s_acc[j][0], s_acc[j][1]));
            mrow1 = fmaxf(mrow1, fmaxf(s_acc[j][2], s_acc[j][3]));
        }
        mrow0 = fmaxf(mrow0, __shfl_xor_sync(0xFFFFFFFF, mrow0, 1));
        mrow0 = fmaxf(mrow0, __shfl_xor_sync(0xFFFFFFFF, mrow0, 2));
        mrow1 = fmaxf(mrow1, __shfl_xor_sync(0xFFFFFFFF, mrow1, 1));
        mrow1 = fmaxf(mrow1, __shfl_xor_sync(0xFFFFFFFF, mrow1, 2));
        float mnew0 = fmaxf(m_run[0], mrow0);
        float mnew1 = fmaxf(m_run[1], mrow1);
        float alpha0 = ex2(m_run[0] - mnew0);
        float alpha1 = ex2(m_run[1] - mnew1);
        float rs0 = 0.f, rs1 = 0.f;
#pragma unroll
        for (int j = 0; j < 16; j++) {
            s_acc[j][0] = ex2(s_acc[j][0] - mnew0);
            s_acc[j][1] = ex2(s_acc[j][1] - mnew0);
            s_acc[j][2] = ex2(s_acc[j][2] - mnew1);
            s_acc[j][3] = ex2(s_acc[j][3] - mnew1);
            rs0 += s_acc[j][0] + s_acc[j][1];
            rs1 += s_acc[j][2] + s_acc[j][3];
        }
        rs0 += __shfl_xor_sync(0xFFFFFFFF, rs0, 1);
        rs0 += __shfl_xor_sync(0xFFFFFFFF, rs0, 2);
        rs1 += __shfl_xor_sync(0xFFFFFFFF, rs1, 1);
        rs1 += __shfl_xor_sync(0xFFFFFFFF, rs1, 2);
        l_run[0] = l_run[0] * alpha0 + rs0;
        l_run[1] = l_run[1] * alpha1 + rs1;
        m_run[0] = mnew0;
        m_run[1] = mnew1;
#pragma unroll
        for (int jj = 0; jj < 16; jj++) {
            o_acc[jj][0] *= alpha0; o_acc[jj][1] *= alpha0;
            o_acc[jj][2] *= alpha1; o_acc[jj][3] *= alpha1;
        }

        uint32_t pa[4][2][4];
#pragma unroll
        for (int vs = 0; vs < 4; vs++)
#pragma unroll
            for (int t = 0; t < 2; t++) {
                int j0 = vs * 4 + 2 * t;
                pa[vs][t][0] = f22u(s_acc[j0][0],   s_acc[j0][1]);
                pa[vs][t][1] = f22u(s_acc[j0][2],   s_acc[j0][3]);
                pa[vs][t][2] = f22u(s_acc[j0+1][0], s_acc[j0+1][1]);
                pa[vs][t][3] = f22u(s_acc[j0+1][2], s_acc[j0+1][3]);
            }

#pragma unroll
        for (int vs = 0; vs < 4; vs++) {
#pragma unroll
            for (int g = 0; g < 8; g++) {
#pragma unroll
                for (int t = 0; t < 2; t++) {
                    uint32_t vb[4];
                    ldsm4(vb, st + 32768 + vs * 8192 + swoff(16 * g + fr_row, t * 2 + fr_ch));
                    mma16816(o_acc[2 * g + 0], pa[vs][t], vb[0], vb[2]);
                    mma16816(o_acc[2 * g + 1], pa[vs][t], vb[1], vb[3]);
                }
            }
        }

        if (kt + 2 < nkt) {
            __syncthreads();
            load_stage(kt + 2);
            CP_COMMIT();
        } else {
            CP_COMMIT();
        }
    }

    float inv0 = 1.0f / l_run[0];
    float inv1 = 1.0f / l_run[1];
    int b = bh >> 4, h = bh & 15;
    int sg0 = qt * 128 + wm + tr;
#pragma unroll
    for (int jj = 0; jj < 16; jj++) {
        int dcol = jj * 8 + tq * 2;
        size_t a0 = ((size_t)(b * Sdim + sg0)) * Hdim + h * 128 + dcol;
        size_t a1 = ((size_t)(b * Sdim + sg0 + 8)) * Hdim + h * 128 + dcol;
        *(__half2*)(g_ctxh + a0) = __floats2half2_rn(o_acc[jj][0] * inv0, o_acc[jj][1] * inv0);
        *(__half2*)(g_ctxh + a1) = __floats2half2_rn(o_acc[jj][2] * inv1, o_acc[jj][3] * inv1);
    }
}

// ============================ launch ============================
extern "C" void kernel_launch(void* const* d_in, const int* in_sizes, int n_in,
                              void* d_out, int out_size) {
    const float* hs            = (const float*)d_in[0];
    const unsigned char* mask  = (const unsigned char*)d_in[1];
    const float* ln1w          = (const float*)d_in[2];
    const float* ln1b          = (const float*)d_in[3];
    const float* wqkv          = (const float*)d_in[4];
    const float* bqkv          = (const float*)d_in[5];
    const float* wdense        = (const float*)d_in[6];
    const float* bdense        = (const float*)d_in[7];
    const float* ln2w          = (const float*)d_in[8];
    const float* ln2b          = (const float*)d_in[9];
    const float* w1            = (const float*)d_in[10];
    const float* b1            = (const float*)d_in[11];
    const float* w2            = (const float*)d_in[12];
    const float* b2            = (const float*)d_in[13];
    float* out = (float*)d_out;

    float *phid;
    __half *pxh, *pctxh, *pinterh, *pqkvh, *pwqkvh, *pwdh, *pw1h, *pw2h;
    cudaGetSymbolAddress((void**)&phid,   g_hidden);
    cudaGetSymbolAddress((void**)&pxh,    g_xh);
    cudaGetSymbolAddress((void**)&pctxh,  g_ctxh);
    cudaGetSymbolAddress((void**)&pinterh, g_interh);
    cudaGetSymbolAddress((void**)&pqkvh,  g_qkvh);
    cudaGetSymbolAddress((void**)&pwqkvh, g_wqkvh);
    cudaGetSymbolAddress((void**)&pwdh,   g_wdh);
    cudaGetSymbolAddress((void**)&pw1h,   g_w1h);
    cudaGetSymbolAddress((void**)&pw2h,   g_w2h);

    cudaFuncSetAttribute(attn_kernel, cudaFuncAttributeMaxDynamicSharedMemorySize, AT_SMEM);
    cudaFuncSetAttribute(hgemm<1>, cudaFuncAttributeMaxDynamicSharedMemorySize, HM_SMEM);
    cudaFuncSetAttribute(hgemm<2>, cudaFuncAttributeMaxDynamicSharedMemorySize, HM_SMEM);
    cudaFuncSetAttribute(hgemm<3>, cudaFuncAttributeMaxDynamicSharedMemorySize, HM_SMEM);

    // mask handling: convert if output carries it
    long long hid_elems = (long long)Mrows * Hdim;           // 8388608
    long long mask_elems = (long long)Sdim * Sdim;           // 4194304
    bool do_mask = ((long long)out_size >= hid_elems + mask_elems);
    int mask_blocks = do_mask ? (int)(mask_elems / 1024) : 0;    // 4 elems/thread
    float* mask_out = do_mask ? (out + hid_elems) : nullptr;

    // consolidated prep: weight cvts + rope table + LN1 + mask
    prep_kernel<<<29184 + mask_blocks, 256>>>(
        wqkv, wdense, w1, w2, hs, ln1w, ln1b, mask, mask_out,
        do_mask ? (int)mask_elems : 0);
    // QKV = x @ wqkv^T + bqkv (half out, fp32 acc)
    hgemm<3><<<dim3(3 * Hdim / GBN, Mrows / GBM), 512, HM_SMEM>>>(
        pxh, pwqkvh, bqkv, nullptr, nullptr, pqkvh, Mrows, 3 * Hdim, Hdim);
    // fused rope (q,k) + V transpose
    rv_kernel<<<18432, 256>>>();
    // HMMA flash attention (Bc=128) -> ctxh
    attn_kernel<<<dim3(Sdim / 128, Bdim * NHdim), 256, AT_SMEM>>>();
    // dense + residual(hidden_states) -> g_hidden (fp32)
    hgemm<2><<<dim3(Hdim / GBN, Mrows / GBM), 512, HM_SMEM>>>(
        pctxh, pwdh, bdense, hs, phid, nullptr, Mrows, Hdim, Hdim);
    // LN2 -> xh
    ln_kernel<<<Mrows, 256>>>(phid, ln2w, ln2b, pxh);
    // FF1 + GELU -> interh (fp16)
    hgemm<1><<<dim3(FFdim / GBN, Mrows / GBM), 512, HM_SMEM>>>(
        pxh, pw1h, b1, nullptr, nullptr, pinterh, Mrows, FFdim, Hdim);
    // FF2 + residual(g_hidden) -> out
    hgemm<2><<<dim3(Hdim / GBN, Mrows / GBM), 512, HM_SMEM>>>(
        pinterh, pw2h, b2, phid, out, nullptr, Mrows, Hdim, FFdim);
}